// round 1
// baseline (speedup 1.0000x reference)
#include <cuda_runtime.h>
#include <math.h>

#define BB 4
#define NN 4096
#define DD 256
#define KTOP 64
#define EPSN 1e-12f

// ---------------- scratch (static device memory; no allocations) ----------------
__device__ float g_normed[(size_t)BB * NN * DD];            // 16 MB
__device__ float g_value [(size_t)BB * NN * DD];            // 16 MB
__device__ float g_cos   [(size_t)BB * NN * NN];            // 256 MB
__device__ float g_sumv_part[BB * 16 * DD];
__device__ float g_sumv [BB * DD];

// ---------------- 1) row L2-normalize ----------------
__global__ void __launch_bounds__(DD) normalize_kernel(const float* __restrict__ x)
{
    int row = blockIdx.x;           // 0..B*N-1
    int d   = threadIdx.x;          // 0..255
    float v = x[(size_t)row * DD + d];
    float s = v * v;
    __shared__ float red[8];
    #pragma unroll
    for (int o = 16; o; o >>= 1) s += __shfl_xor_sync(0xffffffffu, s, o);
    if ((d & 31) == 0) red[d >> 5] = s;
    __syncthreads();
    if (d < 32) {
        float t = (d < 8) ? red[d] : 0.f;
        #pragma unroll
        for (int o = 4; o; o >>= 1) t += __shfl_xor_sync(0xffffffffu, t, o);
        if (d == 0) red[0] = t;
    }
    __syncthreads();
    float norm = sqrtf(red[0]);
    g_normed[(size_t)row * DD + d] = v / fmaxf(norm, EPSN);
}

// ---------------- 2,4) fp32 SGEMM  C[m][n] = sum_k A[m][k]*B[n][k] (+bias[n]) ----------------
// tile 128x128, K-chunk 8, 256 threads, 8x8 per thread. M,N multiples of 128, K of 8.
__global__ void __launch_bounds__(256) sgemm_nt(
    const float* __restrict__ A, const float* __restrict__ Bm,
    const float* __restrict__ bias, float* __restrict__ C,
    int M, int N, int K,
    long long sA, long long sB, long long sC)
{
    A  += (size_t)blockIdx.z * sA;
    Bm += (size_t)blockIdx.z * sB;
    C  += (size_t)blockIdx.z * sC;

    __shared__ float As[8][128];
    __shared__ float Bs[8][128];

    const int t    = threadIdx.x;
    const int row0 = blockIdx.y << 7;
    const int col0 = blockIdx.x << 7;
    const int lr   = t >> 1;          // 0..127 : tile row to load
    const int lw   = (t & 1) << 2;    // 0 or 4 : k offset to load
    const int ty   = t >> 4;          // 0..15
    const int tx   = t & 15;          // 0..15

    float acc[8][8];
    #pragma unroll
    for (int i = 0; i < 8; i++)
        #pragma unroll
        for (int j = 0; j < 8; j++) acc[i][j] = 0.f;

    const float* Ap = A  + (size_t)(row0 + lr) * K + lw;
    const float* Bp = Bm + (size_t)(col0 + lr) * K + lw;

    for (int k0 = 0; k0 < K; k0 += 8) {
        float4 a4 = *(const float4*)(Ap + k0);
        float4 b4 = *(const float4*)(Bp + k0);
        __syncthreads();
        As[lw + 0][lr] = a4.x; As[lw + 1][lr] = a4.y;
        As[lw + 2][lr] = a4.z; As[lw + 3][lr] = a4.w;
        Bs[lw + 0][lr] = b4.x; Bs[lw + 1][lr] = b4.y;
        Bs[lw + 2][lr] = b4.z; Bs[lw + 3][lr] = b4.w;
        __syncthreads();
        #pragma unroll
        for (int kk = 0; kk < 8; kk++) {
            float a[8], b[8];
            *(float4*)&a[0] = *(const float4*)&As[kk][ty << 3];
            *(float4*)&a[4] = *(const float4*)&As[kk][(ty << 3) + 4];
            *(float4*)&b[0] = *(const float4*)&Bs[kk][tx << 3];
            *(float4*)&b[4] = *(const float4*)&Bs[kk][(tx << 3) + 4];
            #pragma unroll
            for (int i = 0; i < 8; i++)
                #pragma unroll
                for (int j = 0; j < 8; j++)
                    acc[i][j] += a[i] * b[j];
        }
    }

    #pragma unroll
    for (int i = 0; i < 8; i++) {
        int r     = row0 + (ty << 3) + i;
        int cbase = col0 + (tx << 3);
        #pragma unroll
        for (int j = 0; j < 8; j += 4) {
            float4 v;
            v.x = acc[i][j + 0]; v.y = acc[i][j + 1];
            v.z = acc[i][j + 2]; v.w = acc[i][j + 3];
            if (bias) {
                v.x += bias[cbase + j + 0]; v.y += bias[cbase + j + 1];
                v.z += bias[cbase + j + 2]; v.w += bias[cbase + j + 3];
            }
            *(float4*)&C[(size_t)r * N + cbase + j] = v;
        }
    }
}

// ---------------- 3) column sum of value per batch (two stages, deterministic) ----------------
__global__ void __launch_bounds__(DD) sumv_part_kernel()
{
    int b = blockIdx.y;         // 0..3
    int c = blockIdx.x;         // 0..15
    int e = threadIdx.x;        // 0..255
    const float* base = g_value + (size_t)b * NN * DD + (size_t)c * 256 * DD + e;
    float s = 0.f;
    #pragma unroll 8
    for (int n = 0; n < 256; n++) s += base[(size_t)n * DD];
    g_sumv_part[(b * 16 + c) * DD + e] = s;
}

__global__ void __launch_bounds__(DD) sumv_reduce_kernel()
{
    int b = blockIdx.x, e = threadIdx.x;
    float s = 0.f;
    #pragma unroll
    for (int c = 0; c < 16; c++) s += g_sumv_part[(b * 16 + c) * DD + e];
    g_sumv[b * DD + e] = s;
}

// ---------------- 5) per-row: exact top-64 select + fused sparse-softmax output ----------------
// out[b,n,:] = ( sumV[b,:] + sum_k (exp(v_k)-1)*value[b,i_k,:] ) / ( (N-K) + sum_k exp(v_k) )
__global__ void __launch_bounds__(256) topk_out_kernel(float* __restrict__ out)
{
    const int n = blockIdx.x;
    const int b = blockIdx.y;
    const int t = threadIdx.x;

    __shared__ unsigned keys[NN];        // 16 KB
    __shared__ int      red_i[10];
    __shared__ float    red_f[8];
    __shared__ int      sel_idx[KTOP];
    __shared__ unsigned sel_key[KTOP];
    __shared__ float    sel_w[KTOP];
    __shared__ int      eq_idx[128];
    __shared__ int      cnt_gt, cnt_eq;
    __shared__ float    Zsh;

    const float* row = g_cos + ((size_t)b * NN + n) * NN;

    // load row, transform to order-preserving unsigned keys (descending float == descending key)
    for (int i = t; i < NN; i += 256) {
        unsigned x = __float_as_uint(row[i]);
        keys[i] = (x & 0x80000000u) ? ~x : (x | 0x80000000u);
    }
    if (t == 0) { cnt_gt = 0; cnt_eq = 0; }
    __syncthreads();

    // binary search for the 64th-largest key (largest u with count_ge(u) >= KTOP)
    unsigned lo = 0u, hi = 0xFFFFFFFFu;
    while (lo < hi) {
        unsigned span = hi - lo;
        unsigned mid  = lo + (span >> 1) + (span & 1u);   // upper mid, overflow-safe
        int c = 0;
        #pragma unroll
        for (int i = t; i < NN; i += 256) c += (keys[i] >= mid);
        #pragma unroll
        for (int o = 16; o; o >>= 1) c += __shfl_xor_sync(0xffffffffu, c, o);
        if ((t & 31) == 0) red_i[t >> 5] = c;
        __syncthreads();
        if (t == 0) {
            int s = 0;
            #pragma unroll
            for (int w = 0; w < 8; w++) s += red_i[w];
            red_i[8] = s;
        }
        __syncthreads();
        int total = red_i[8];
        if (total >= KTOP) lo = mid; else hi = mid - 1;
        __syncthreads();
    }
    const unsigned ustar = lo;

    // collect strict-greater and equal elements
    for (int i = t; i < NN; i += 256) {
        unsigned u = keys[i];
        if (u > ustar) {
            int p = atomicAdd(&cnt_gt, 1);
            sel_idx[p] = i;
            sel_key[p] = u;
        } else if (u == ustar) {
            int p = atomicAdd(&cnt_eq, 1);
            if (p < 128) eq_idx[p] = i;
        }
    }
    __syncthreads();

    const int ngt = cnt_gt;
    const int r   = KTOP - ngt;          // >= 1 by construction
    if (t == 0) {
        // stable tie-break: smallest indices first (matches jax.lax.top_k)
        int ne = cnt_eq < 128 ? cnt_eq : 128;
        for (int a = 1; a < ne; a++) {
            int v = eq_idx[a]; int c2 = a - 1;
            while (c2 >= 0 && eq_idx[c2] > v) { eq_idx[c2 + 1] = eq_idx[c2]; c2--; }
            eq_idx[c2 + 1] = v;
        }
        for (int a = 0; a < r; a++) {
            sel_idx[ngt + a] = eq_idx[a];
            sel_key[ngt + a] = ustar;
        }
    }
    __syncthreads();

    // weights and partition function
    float e_val = 0.f;
    if (t < KTOP) {
        unsigned u = sel_key[t];
        float v = (u & 0x80000000u) ? __uint_as_float(u & 0x7FFFFFFFu)
                                    : __uint_as_float(~u);
        e_val = expf(v);
        sel_w[t] = e_val - 1.0f;
    }
    float s = e_val;
    #pragma unroll
    for (int o = 16; o; o >>= 1) s += __shfl_xor_sync(0xffffffffu, s, o);
    if ((t & 31) == 0) red_f[t >> 5] = s;
    __syncthreads();
    if (t == 0) {
        float z = (float)(NN - KTOP);
        #pragma unroll
        for (int w = 0; w < 8; w++) z += red_f[w];
        Zsh = z;
    }
    __syncthreads();

    // fused output: global value-sum + weighted gather of 64 value rows
    const float* Vb = g_value + (size_t)b * NN * DD;
    float acc = g_sumv[b * DD + t];
    const float invZ = 1.0f / Zsh;
    #pragma unroll 8
    for (int k = 0; k < KTOP; k++)
        acc += sel_w[k] * Vb[(size_t)sel_idx[k] * DD + t];
    out[((size_t)b * NN + n) * DD + t] = acc * invZ;
}

// ---------------- launch ----------------
extern "C" void kernel_launch(void* const* d_in, const int* in_sizes, int n_in,
                              void* d_out, int out_size)
{
    const float* x    = (const float*)d_in[0];   // [4,4096,256]
    const float* W    = (const float*)d_in[1];   // [256,256]
    const float* bias = (const float*)d_in[2];   // [256]
    float*       out  = (float*)d_out;           // [4,4096,256]

    float *p_normed, *p_value, *p_cos;
    cudaGetSymbolAddress((void**)&p_normed, g_normed);
    cudaGetSymbolAddress((void**)&p_value,  g_value);
    cudaGetSymbolAddress((void**)&p_cos,    g_cos);

    // 1) normalize rows of x
    normalize_kernel<<<BB * NN, DD>>>(x);

    // 2) value = x @ W^T + b      (M=16384, N=256, K=256)
    sgemm_nt<<<dim3(DD / 128, (BB * NN) / 128, 1), 256>>>(
        x, W, bias, p_value, BB * NN, DD, DD, 0, 0, 0);

    // 3) per-batch column sums of value
    sumv_part_kernel<<<dim3(16, BB), DD>>>();
    sumv_reduce_kernel<<<BB, DD>>>();

    // 4) cos = normed @ normed^T per batch   (M=N=4096, K=256)
    sgemm_nt<<<dim3(NN / 128, NN / 128, BB), 256>>>(
        p_normed, p_normed, nullptr, p_cos, NN, NN, DD,
        (long long)NN * DD, (long long)NN * DD, (long long)NN * NN);

    // 5) top-64 select + fused sparse softmax output
    topk_out_kernel<<<dim3(NN, BB), 256>>>(out);
}

// round 4
// speedup vs baseline: 1.8776x; 1.8776x over previous
#include <cuda_runtime.h>
#include <cuda_bf16.h>
#include <cstdint>
#include <math.h>

#define BB 4
#define NN 4096
#define DD 256
#define KTOP 64
#define EPSN 1e-12f

#define KPACK 768             // [hi|hi|lo] vs [hi|lo|hi]
#define KC 64                 // k-chunk (128 bytes of bf16 per row)
#define NCHUNK (KPACK / KC)   // 12

// ---------------- scratch (static device memory; no allocations) ----------------
__device__ float          g_value[(size_t)BB * NN * DD];          // 16 MB
__device__ float          g_cos  [(size_t)BB * NN * NN];          // 256 MB
__device__ __nv_bfloat16  g_packA[(size_t)BB * NN * KPACK];       // 25 MB
__device__ __nv_bfloat16  g_packB[(size_t)BB * NN * KPACK];       // 25 MB
__device__ float          g_sumv_part[BB * 16 * DD];
__device__ float          g_sumv[BB * DD];

__device__ __forceinline__ uint32_t smem_to_u32(const void* p) {
    uint32_t a;
    asm("{ .reg .u64 t; cvta.to.shared.u64 t, %1; cvt.u32.u64 %0, t; }" : "=r"(a) : "l"(p));
    return a;
}
__device__ __forceinline__ void ldsm4(uint32_t& r0, uint32_t& r1, uint32_t& r2, uint32_t& r3, uint32_t addr) {
    asm volatile("ldmatrix.sync.aligned.m8n8.x4.shared.b16 {%0,%1,%2,%3}, [%4];"
        : "=r"(r0), "=r"(r1), "=r"(r2), "=r"(r3) : "r"(addr));
}
__device__ __forceinline__ void mma16816(float* d, const uint32_t* a, const uint32_t* b) {
    asm volatile("mma.sync.aligned.m16n8k16.row.col.f32.bf16.bf16.f32 "
        "{%0,%1,%2,%3}, {%4,%5,%6,%7}, {%8,%9}, {%0,%1,%2,%3};"
        : "+f"(d[0]), "+f"(d[1]), "+f"(d[2]), "+f"(d[3])
        : "r"(a[0]), "r"(a[1]), "r"(a[2]), "r"(a[3]), "r"(b[0]), "r"(b[1]));
}

// ---------------- 1) fused row L2-normalize + bf16 hi/lo pack ----------------
__global__ void __launch_bounds__(DD) normalize_pack_kernel(const float* __restrict__ x)
{
    int row = blockIdx.x;
    int d   = threadIdx.x;
    float v = x[(size_t)row * DD + d];
    float s = v * v;
    __shared__ float red[8];
    #pragma unroll
    for (int o = 16; o; o >>= 1) s += __shfl_xor_sync(0xffffffffu, s, o);
    if ((d & 31) == 0) red[d >> 5] = s;
    __syncthreads();
    if (d < 32) {
        float t = (d < 8) ? red[d] : 0.f;
        #pragma unroll
        for (int o = 4; o; o >>= 1) t += __shfl_xor_sync(0xffffffffu, t, o);
        if (d == 0) red[0] = t;
    }
    __syncthreads();
    float norm = sqrtf(red[0]);
    float nv = v / fmaxf(norm, EPSN);

    __nv_bfloat16 hi = __float2bfloat16(nv);
    __nv_bfloat16 lo = __float2bfloat16(nv - __bfloat162float(hi));

    size_t base = (size_t)row * KPACK;
    g_packA[base + d]       = hi;
    g_packA[base + 256 + d] = hi;
    g_packA[base + 512 + d] = lo;
    g_packB[base + d]       = hi;
    g_packB[base + 256 + d] = lo;
    g_packB[base + 512 + d] = hi;
}

// ---------------- 2) fp32 SGEMM for value = x@W^T + b ----------------
__global__ void __launch_bounds__(256) sgemm_nt(
    const float* __restrict__ A, const float* __restrict__ Bm,
    const float* __restrict__ bias, float* __restrict__ C,
    int M, int N, int K)
{
    __shared__ float As[8][128];
    __shared__ float Bs[8][128];

    const int t    = threadIdx.x;
    const int row0 = blockIdx.y << 7;
    const int col0 = blockIdx.x << 7;
    const int lr   = t >> 1;
    const int lw   = (t & 1) << 2;
    const int ty   = t >> 4;
    const int tx   = t & 15;

    float acc[8][8];
    #pragma unroll
    for (int i = 0; i < 8; i++)
        #pragma unroll
        for (int j = 0; j < 8; j++) acc[i][j] = 0.f;

    const float* Ap = A  + (size_t)(row0 + lr) * K + lw;
    const float* Bp = Bm + (size_t)(col0 + lr) * K + lw;

    for (int k0 = 0; k0 < K; k0 += 8) {
        float4 a4 = *(const float4*)(Ap + k0);
        float4 b4 = *(const float4*)(Bp + k0);
        __syncthreads();
        As[lw + 0][lr] = a4.x; As[lw + 1][lr] = a4.y;
        As[lw + 2][lr] = a4.z; As[lw + 3][lr] = a4.w;
        Bs[lw + 0][lr] = b4.x; Bs[lw + 1][lr] = b4.y;
        Bs[lw + 2][lr] = b4.z; Bs[lw + 3][lr] = b4.w;
        __syncthreads();
        #pragma unroll
        for (int kk = 0; kk < 8; kk++) {
            float a[8], b[8];
            *(float4*)&a[0] = *(const float4*)&As[kk][ty << 3];
            *(float4*)&a[4] = *(const float4*)&As[kk][(ty << 3) + 4];
            *(float4*)&b[0] = *(const float4*)&Bs[kk][tx << 3];
            *(float4*)&b[4] = *(const float4*)&Bs[kk][(tx << 3) + 4];
            #pragma unroll
            for (int i = 0; i < 8; i++)
                #pragma unroll
                for (int j = 0; j < 8; j++)
                    acc[i][j] += a[i] * b[j];
        }
    }

    #pragma unroll
    for (int i = 0; i < 8; i++) {
        int r     = row0 + (ty << 3) + i;
        int cbase = col0 + (tx << 3);
        #pragma unroll
        for (int j = 0; j < 8; j += 4) {
            float4 v;
            v.x = acc[i][j + 0] + bias[cbase + j + 0];
            v.y = acc[i][j + 1] + bias[cbase + j + 1];
            v.z = acc[i][j + 2] + bias[cbase + j + 2];
            v.w = acc[i][j + 3] + bias[cbase + j + 3];
            *(float4*)&C[(size_t)r * N + cbase + j] = v;
        }
    }
}

// ---------------- 3) column sums of value ----------------
__global__ void __launch_bounds__(DD) sumv_part_kernel()
{
    int b = blockIdx.y, c = blockIdx.x, e = threadIdx.x;
    const float* base = g_value + (size_t)b * NN * DD + (size_t)c * 256 * DD + e;
    float s = 0.f;
    #pragma unroll 8
    for (int n = 0; n < 256; n++) s += base[(size_t)n * DD];
    g_sumv_part[(b * 16 + c) * DD + e] = s;
}
__global__ void __launch_bounds__(DD) sumv_reduce_kernel()
{
    int b = blockIdx.x, e = threadIdx.x;
    float s = 0.f;
    #pragma unroll
    for (int c = 0; c < 16; c++) s += g_sumv_part[(b * 16 + c) * DD + e];
    g_sumv[b * DD + e] = s;
}

// ---------------- 4) bf16 mma.sync GEMM: cos = packA @ packB^T (K=768 split) ----------------
// Symmetric: only lower-triangle 128x128 CTA tiles (bx<=by); each writes tile + mirror.
// 256 thr = 8 warps (4 M x 2 N), warp tile 32x64, m16n8k16 atoms.
__global__ void __launch_bounds__(256, 2) cosmma_kernel(
    const __nv_bfloat16* __restrict__ Apk, const __nv_bfloat16* __restrict__ Bpk,
    float* __restrict__ C)
{
    extern __shared__ char smem[];   // 2 stages x (A 16KB + B 16KB); epilogue reuses 67584B
    const uint32_t sb = smem_to_u32(smem);

    const int tid  = threadIdx.x;
    const int wid  = tid >> 5;
    const int lane = tid & 31;
    const int wm   = wid & 3;        // 0..3 (M)
    const int wn   = wid >> 2;       // 0..1 (N)
    const int b    = blockIdx.z;

    // triangular decode: blockIdx.x -> (bx <= by)
    int i  = blockIdx.x;
    int by = (int)((sqrtf(8.f * (float)i + 1.f) - 1.f) * 0.5f);
    while ((by + 1) * (by + 2) / 2 <= i) by++;
    while (by * (by + 1) / 2 > i) by--;
    int bx = i - by * (by + 1) / 2;
    const int m0 = by * 128;
    const int n0 = bx * 128;

    const __nv_bfloat16* Agl = Apk + ((size_t)b * NN + m0) * KPACK;
    const __nv_bfloat16* Bgl = Bpk + ((size_t)b * NN + n0) * KPACK;

    // loader: chunk c into stage s (128 rows x 128B, SW128 swizzle)
    auto load_chunk = [&](int c, int s) {
        const char* ga = (const char*)Agl + (size_t)c * 128;
        const char* gb = (const char*)Bgl + (size_t)c * 128;
        char* sa = smem + s * 32768;
        char* sbm = sa + 16384;
        #pragma unroll
        for (int k = 0; k < 4; k++) {
            int idx = tid + 256 * k;
            int r = idx >> 3, j = idx & 7;
            uint4 va = *(const uint4*)(ga + (size_t)r * (KPACK * 2) + j * 16);
            uint4 vb = *(const uint4*)(gb + (size_t)r * (KPACK * 2) + j * 16);
            uint32_t off = r * 128 + ((j ^ (r & 7)) << 4);
            *(uint4*)(sa + off)  = va;
            *(uint4*)(sbm + off) = vb;
        }
    };

    float acc[2][8][4];
    #pragma unroll
    for (int ia = 0; ia < 2; ia++)
        #pragma unroll
        for (int j = 0; j < 8; j++)
            #pragma unroll
            for (int q = 0; q < 4; q++) acc[ia][j][q] = 0.f;

    // per-lane invariant pieces of ldmatrix addresses
    const int arow_lo = (lane & 7) + ((lane >> 3) & 1) * 8;   // A: row within atom
    const int a_cc_add = (lane >> 4);                          // A: chunk select
    const int brow_lo = (lane & 7) + ((lane >> 4) ? 8 : 0);    // B
    const int b_cc_add = ((lane >> 3) & 1);

    load_chunk(0, 0);
    __syncthreads();

    for (int c = 0; c < NCHUNK; c++) {
        int s = c & 1;
        if (c + 1 < NCHUNK) load_chunk(c + 1, s ^ 1);

        const uint32_t abase = sb + s * 32768;
        const uint32_t bbase = abase + 16384;

        #pragma unroll
        for (int ks = 0; ks < 4; ks++) {
            uint32_t af[2][4], bf[8][2];
            #pragma unroll
            for (int ia = 0; ia < 2; ia++) {
                int row = wm * 32 + ia * 16 + arow_lo;
                uint32_t cc = 2 * ks + a_cc_add;
                uint32_t addr = abase + row * 128 + ((cc << 4) ^ ((row & 7) << 4));
                ldsm4(af[ia][0], af[ia][1], af[ia][2], af[ia][3], addr);
            }
            #pragma unroll
            for (int L = 0; L < 4; L++) {
                int row = wn * 64 + L * 16 + brow_lo;
                uint32_t cc = 2 * ks + b_cc_add;
                uint32_t addr = bbase + row * 128 + ((cc << 4) ^ ((row & 7) << 4));
                ldsm4(bf[2 * L][0], bf[2 * L][1], bf[2 * L + 1][0], bf[2 * L + 1][1], addr);
            }
            #pragma unroll
            for (int ia = 0; ia < 2; ia++)
                #pragma unroll
                for (int j = 0; j < 8; j++)
                    mma16816(acc[ia][j], af[ia], bf[j]);
        }
        __syncthreads();
    }

    // ---- epilogue: stage 128x128 fp32 in smem (row stride 132), write tile + mirror ----
    float* st = (float*)smem;
    const int g = lane >> 2, q = lane & 3;
    #pragma unroll
    for (int ia = 0; ia < 2; ia++) {
        #pragma unroll
        for (int j = 0; j < 8; j++) {
            int row = wm * 32 + ia * 16 + g;
            int col = wn * 64 + j * 8 + q * 2;
            st[row * 132 + col]           = acc[ia][j][0];
            st[row * 132 + col + 1]       = acc[ia][j][1];
            st[(row + 8) * 132 + col]     = acc[ia][j][2];
            st[(row + 8) * 132 + col + 1] = acc[ia][j][3];
        }
    }
    __syncthreads();

    float* Cb = C + (size_t)b * NN * NN;
    #pragma unroll
    for (int it = 0; it < 16; it++) {
        int idx = tid + 256 * it;
        int row = idx >> 5, cq = idx & 31;
        float4 v = *(float4*)&st[row * 132 + cq * 4];
        *(float4*)&Cb[(size_t)(m0 + row) * NN + n0 + cq * 4] = v;
    }
    if (bx != by) {
        #pragma unroll
        for (int it = 0; it < 16; it++) {
            int idx = tid + 256 * it;
            int row = idx >> 5, cq = idx & 31;   // row: n-dir index, cq: m-dir float4
            float4 v;
            v.x = st[(cq * 4 + 0) * 132 + row];
            v.y = st[(cq * 4 + 1) * 132 + row];
            v.z = st[(cq * 4 + 2) * 132 + row];
            v.w = st[(cq * 4 + 3) * 132 + row];
            *(float4*)&Cb[(size_t)(n0 + row) * NN + m0 + cq * 4] = v;
        }
    }
}

// ---------------- 5) per-row: exact top-64 select + fused sparse-softmax output ----------------
__global__ void __launch_bounds__(256) topk_out_kernel(float* __restrict__ out)
{
    const int n = blockIdx.x;
    const int b = blockIdx.y;
    const int t = threadIdx.x;

    __shared__ int      red_i[10];
    __shared__ float    red_f[8];
    __shared__ int      sel_idx[KTOP];
    __shared__ unsigned sel_key[KTOP];
    __shared__ float    sel_w[KTOP];
    __shared__ int      eq_idx[128];
    __shared__ int      cnt_gt, cnt_eq;
    __shared__ float    Zsh;

    const float* row = g_cos + ((size_t)b * NN + n) * NN;

    unsigned kreg[16];
    #pragma unroll
    for (int j = 0; j < 16; j++) {
        unsigned x = __float_as_uint(row[t + 256 * j]);
        kreg[j] = (x & 0x80000000u) ? ~x : (x | 0x80000000u);
    }
    if (t == 0) { cnt_gt = 0; cnt_eq = 0; }
    __syncthreads();

    unsigned lo = 0u, hi = 0xFFFFFFFFu;
    while (lo < hi) {
        unsigned span = hi - lo;
        unsigned mid  = lo + (span >> 1) + (span & 1u);
        int c = 0;
        #pragma unroll
        for (int j = 0; j < 16; j++) c += (kreg[j] >= mid);
        #pragma unroll
        for (int o = 16; o; o >>= 1) c += __shfl_xor_sync(0xffffffffu, c, o);
        if ((t & 31) == 0) red_i[t >> 5] = c;
        __syncthreads();
        if (t == 0) {
            int s = 0;
            #pragma unroll
            for (int w = 0; w < 8; w++) s += red_i[w];
            red_i[8] = s;
        }
        __syncthreads();
        if (red_i[8] >= KTOP) lo = mid; else hi = mid - 1;
        __syncthreads();
    }
    const unsigned ustar = lo;

    #pragma unroll
    for (int j = 0; j < 16; j++) {
        unsigned u = kreg[j];
        if (u > ustar) {
            int p = atomicAdd(&cnt_gt, 1);
            sel_idx[p] = t + 256 * j;
            sel_key[p] = u;
        } else if (u == ustar) {
            int p = atomicAdd(&cnt_eq, 1);
            if (p < 128) eq_idx[p] = t + 256 * j;
        }
    }
    __syncthreads();

    const int ngt = cnt_gt;
    const int r   = KTOP - ngt;
    if (t == 0) {
        int ne = cnt_eq < 128 ? cnt_eq : 128;
        for (int a = 1; a < ne; a++) {
            int v = eq_idx[a]; int c2 = a - 1;
            while (c2 >= 0 && eq_idx[c2] > v) { eq_idx[c2 + 1] = eq_idx[c2]; c2--; }
            eq_idx[c2 + 1] = v;
        }
        for (int a = 0; a < r; a++) { sel_idx[ngt + a] = eq_idx[a]; sel_key[ngt + a] = ustar; }
    }
    __syncthreads();

    float e_val = 0.f;
    if (t < KTOP) {
        unsigned u = sel_key[t];
        float v = (u & 0x80000000u) ? __uint_as_float(u & 0x7FFFFFFFu) : __uint_as_float(~u);
        e_val = expf(v);
        sel_w[t] = e_val - 1.0f;
    }
    float s = e_val;
    #pragma unroll
    for (int o = 16; o; o >>= 1) s += __shfl_xor_sync(0xffffffffu, s, o);
    if ((t & 31) == 0) red_f[t >> 5] = s;
    __syncthreads();
    if (t == 0) {
        float z = (float)(NN - KTOP);
        #pragma unroll
        for (int w = 0; w < 8; w++) z += red_f[w];
        Zsh = z;
    }
    __syncthreads();

    const float* Vb = g_value + (size_t)b * NN * DD;
    float acc = g_sumv[b * DD + t];
    const float invZ = 1.0f / Zsh;
    #pragma unroll 8
    for (int k = 0; k < KTOP; k++)
        acc += sel_w[k] * Vb[(size_t)sel_idx[k] * DD + t];
    out[((size_t)b * NN + n) * DD + t] = acc * invZ;
}

// ---------------- launch ----------------
extern "C" void kernel_launch(void* const* d_in, const int* in_sizes, int n_in,
                              void* d_out, int out_size)
{
    const float* x    = (const float*)d_in[0];   // [4,4096,256]
    const float* W    = (const float*)d_in[1];   // [256,256]
    const float* bias = (const float*)d_in[2];   // [256]
    float*       out  = (float*)d_out;           // [4,4096,256]

    float *p_value, *p_cos;
    __nv_bfloat16 *p_packA, *p_packB;
    cudaGetSymbolAddress((void**)&p_value, g_value);
    cudaGetSymbolAddress((void**)&p_cos,   g_cos);
    cudaGetSymbolAddress((void**)&p_packA, g_packA);
    cudaGetSymbolAddress((void**)&p_packB, g_packB);

    const int COSMMA_SMEM = 67584;   // max(2*32KB mainloop, 128*132*4 epilogue)
    cudaFuncSetAttribute(cosmma_kernel, cudaFuncAttributeMaxDynamicSharedMemorySize, COSMMA_SMEM);

    // 1) normalize + hi/lo bf16 pack
    normalize_pack_kernel<<<BB * NN, DD>>>(x);

    // 2) value = x @ W^T + b
    sgemm_nt<<<dim3(DD / 128, (BB * NN) / 128, 1), 256>>>(x, W, bias, p_value, BB * NN, DD, DD);

    // 3) per-batch column sums of value
    sumv_part_kernel<<<dim3(16, BB), DD>>>();
    sumv_reduce_kernel<<<BB, DD>>>();

    // 4) cos = packA @ packB^T  (mma.sync bf16, symmetric lower-triangle tiles)
    cosmma_kernel<<<dim3((NN / 128) * (NN / 128 + 1) / 2, 1, BB), 256, COSMMA_SMEM>>>(p_packA, p_packB, p_cos);

    // 5) top-64 select + fused sparse softmax output
    topk_out_kernel<<<dim3(NN, BB), 256>>>(out);
}

// round 5
// speedup vs baseline: 2.9146x; 1.5523x over previous
#include <cuda_runtime.h>
#include <cuda_bf16.h>
#include <cstdint>
#include <math.h>

#define BB 4
#define NN 4096
#define DD 256
#define KTOP 64
#define EPSN 1e-12f

#define KPACK 768             // [hi|hi|lo] vs [hi|lo|hi]
#define KC 64                 // k-chunk (128 bytes of bf16 per row)
#define NCHUNK (KPACK / KC)   // 12

// ---------------- scratch (static device memory; no allocations) ----------------
__device__ float          g_value[(size_t)BB * NN * DD];          // 16 MB
__device__ float          g_cos  [(size_t)BB * NN * NN];          // 256 MB
__device__ __nv_bfloat16  g_packA[(size_t)BB * NN * KPACK];       // 25 MB
__device__ __nv_bfloat16  g_packB[(size_t)BB * NN * KPACK];       // 25 MB
__device__ float          g_sumv_part[BB * 16 * DD];
__device__ float          g_sumv[BB * DD];

__device__ __forceinline__ uint32_t smem_to_u32(const void* p) {
    uint32_t a;
    asm("{ .reg .u64 t; cvta.to.shared.u64 t, %1; cvt.u32.u64 %0, t; }" : "=r"(a) : "l"(p));
    return a;
}
__device__ __forceinline__ void ldsm4(uint32_t& r0, uint32_t& r1, uint32_t& r2, uint32_t& r3, uint32_t addr) {
    asm volatile("ldmatrix.sync.aligned.m8n8.x4.shared.b16 {%0,%1,%2,%3}, [%4];"
        : "=r"(r0), "=r"(r1), "=r"(r2), "=r"(r3) : "r"(addr));
}
__device__ __forceinline__ void mma16816(float* d, const uint32_t* a, const uint32_t* b) {
    asm volatile("mma.sync.aligned.m16n8k16.row.col.f32.bf16.bf16.f32 "
        "{%0,%1,%2,%3}, {%4,%5,%6,%7}, {%8,%9}, {%0,%1,%2,%3};"
        : "+f"(d[0]), "+f"(d[1]), "+f"(d[2]), "+f"(d[3])
        : "r"(a[0]), "r"(a[1]), "r"(a[2]), "r"(a[3]), "r"(b[0]), "r"(b[1]));
}
__device__ __forceinline__ void cp_async16(uint32_t saddr, const void* gptr) {
    asm volatile("cp.async.cg.shared.global [%0], [%1], 16;" :: "r"(saddr), "l"(gptr) : "memory");
}
#define CP_COMMIT() asm volatile("cp.async.commit_group;" ::: "memory")
#define CP_WAIT(N)  asm volatile("cp.async.wait_group %0;" :: "n"(N) : "memory")

// ---------------- 1) fused row L2-normalize + bf16 hi/lo pack ----------------
__global__ void __launch_bounds__(DD) normalize_pack_kernel(const float* __restrict__ x)
{
    int row = blockIdx.x;
    int d   = threadIdx.x;
    float v = x[(size_t)row * DD + d];
    float s = v * v;
    __shared__ float red[8];
    #pragma unroll
    for (int o = 16; o; o >>= 1) s += __shfl_xor_sync(0xffffffffu, s, o);
    if ((d & 31) == 0) red[d >> 5] = s;
    __syncthreads();
    if (d < 32) {
        float t = (d < 8) ? red[d] : 0.f;
        #pragma unroll
        for (int o = 4; o; o >>= 1) t += __shfl_xor_sync(0xffffffffu, t, o);
        if (d == 0) red[0] = t;
    }
    __syncthreads();
    float norm = sqrtf(red[0]);
    float nv = v / fmaxf(norm, EPSN);

    __nv_bfloat16 hi = __float2bfloat16(nv);
    __nv_bfloat16 lo = __float2bfloat16(nv - __bfloat162float(hi));

    size_t base = (size_t)row * KPACK;
    g_packA[base + d]       = hi;
    g_packA[base + 256 + d] = hi;
    g_packA[base + 512 + d] = lo;
    g_packB[base + d]       = hi;
    g_packB[base + 256 + d] = lo;
    g_packB[base + 512 + d] = hi;
}

// ---------------- 2) fp32 SGEMM for value = x@W^T + b ----------------
__global__ void __launch_bounds__(256) sgemm_nt(
    const float* __restrict__ A, const float* __restrict__ Bm,
    const float* __restrict__ bias, float* __restrict__ C,
    int M, int N, int K)
{
    __shared__ float As[8][128];
    __shared__ float Bs[8][128];

    const int t    = threadIdx.x;
    const int row0 = blockIdx.y << 7;
    const int col0 = blockIdx.x << 7;
    const int lr   = t >> 1;
    const int lw   = (t & 1) << 2;
    const int ty   = t >> 4;
    const int tx   = t & 15;

    float acc[8][8];
    #pragma unroll
    for (int i = 0; i < 8; i++)
        #pragma unroll
        for (int j = 0; j < 8; j++) acc[i][j] = 0.f;

    const float* Ap = A  + (size_t)(row0 + lr) * K + lw;
    const float* Bp = Bm + (size_t)(col0 + lr) * K + lw;

    for (int k0 = 0; k0 < K; k0 += 8) {
        float4 a4 = *(const float4*)(Ap + k0);
        float4 b4 = *(const float4*)(Bp + k0);
        __syncthreads();
        As[lw + 0][lr] = a4.x; As[lw + 1][lr] = a4.y;
        As[lw + 2][lr] = a4.z; As[lw + 3][lr] = a4.w;
        Bs[lw + 0][lr] = b4.x; Bs[lw + 1][lr] = b4.y;
        Bs[lw + 2][lr] = b4.z; Bs[lw + 3][lr] = b4.w;
        __syncthreads();
        #pragma unroll
        for (int kk = 0; kk < 8; kk++) {
            float a[8], b[8];
            *(float4*)&a[0] = *(const float4*)&As[kk][ty << 3];
            *(float4*)&a[4] = *(const float4*)&As[kk][(ty << 3) + 4];
            *(float4*)&b[0] = *(const float4*)&Bs[kk][tx << 3];
            *(float4*)&b[4] = *(const float4*)&Bs[kk][(tx << 3) + 4];
            #pragma unroll
            for (int i = 0; i < 8; i++)
                #pragma unroll
                for (int j = 0; j < 8; j++)
                    acc[i][j] += a[i] * b[j];
        }
    }

    #pragma unroll
    for (int i = 0; i < 8; i++) {
        int r     = row0 + (ty << 3) + i;
        int cbase = col0 + (tx << 3);
        #pragma unroll
        for (int j = 0; j < 8; j += 4) {
            float4 v;
            v.x = acc[i][j + 0] + bias[cbase + j + 0];
            v.y = acc[i][j + 1] + bias[cbase + j + 1];
            v.z = acc[i][j + 2] + bias[cbase + j + 2];
            v.w = acc[i][j + 3] + bias[cbase + j + 3];
            *(float4*)&C[(size_t)r * N + cbase + j] = v;
        }
    }
}

// ---------------- 3) column sums of value ----------------
__global__ void __launch_bounds__(DD) sumv_part_kernel()
{
    int b = blockIdx.y, c = blockIdx.x, e = threadIdx.x;
    const float* base = g_value + (size_t)b * NN * DD + (size_t)c * 256 * DD + e;
    float s = 0.f;
    #pragma unroll 8
    for (int n = 0; n < 256; n++) s += base[(size_t)n * DD];
    g_sumv_part[(b * 16 + c) * DD + e] = s;
}
__global__ void __launch_bounds__(DD) sumv_reduce_kernel()
{
    int b = blockIdx.x, e = threadIdx.x;
    float s = 0.f;
    #pragma unroll
    for (int c = 0; c < 16; c++) s += g_sumv_part[(b * 16 + c) * DD + e];
    g_sumv[b * DD + e] = s;
}

// ---------------- 4) bf16 mma.sync GEMM: cos = packA @ packB^T (K=768 split) ----------------
// Symmetric: only lower-triangle 128x128 CTA tiles (bx<=by); each writes tile + mirror.
// cp.async double-buffered mainloop for real load/MMA overlap.
__global__ void __launch_bounds__(256, 2) cosmma_kernel(
    const __nv_bfloat16* __restrict__ Apk, const __nv_bfloat16* __restrict__ Bpk,
    float* __restrict__ C)
{
    extern __shared__ char smem[];   // 2 stages x (A 16KB + B 16KB); epilogue reuses 67584B
    const uint32_t sb = smem_to_u32(smem);

    const int tid  = threadIdx.x;
    const int wid  = tid >> 5;
    const int lane = tid & 31;
    const int wm   = wid & 3;        // 0..3 (M)
    const int wn   = wid >> 2;       // 0..1 (N)
    const int b    = blockIdx.z;

    // triangular decode: blockIdx.x -> (bx <= by)
    int i  = blockIdx.x;
    int by = (int)((sqrtf(8.f * (float)i + 1.f) - 1.f) * 0.5f);
    while ((by + 1) * (by + 2) / 2 <= i) by++;
    while (by * (by + 1) / 2 > i) by--;
    int bx = i - by * (by + 1) / 2;
    const int m0 = by * 128;
    const int n0 = bx * 128;

    const __nv_bfloat16* Agl = Apk + ((size_t)b * NN + m0) * KPACK;
    const __nv_bfloat16* Bgl = Bpk + ((size_t)b * NN + n0) * KPACK;

    // per-thread constant pieces of the async-copy addressing
    const int lr = tid >> 3;            // row this thread loads (0..31 step per k)
    const int lj = tid & 7;             // 16B column chunk

    auto load_chunk_async = [&](int c, int s) {
        const char* ga = (const char*)Agl + (size_t)c * 128;
        const char* gb = (const char*)Bgl + (size_t)c * 128;
        uint32_t sa = sb + s * 32768;
        uint32_t sbm = sa + 16384;
        #pragma unroll
        for (int k = 0; k < 4; k++) {
            int r = lr + 32 * k;
            uint32_t off = r * 128 + ((lj ^ (r & 7)) << 4);
            cp_async16(sa + off,  ga + (size_t)r * (KPACK * 2) + lj * 16);
            cp_async16(sbm + off, gb + (size_t)r * (KPACK * 2) + lj * 16);
        }
    };

    float acc[2][8][4];
    #pragma unroll
    for (int ia = 0; ia < 2; ia++)
        #pragma unroll
        for (int j = 0; j < 8; j++)
            #pragma unroll
            for (int q = 0; q < 4; q++) acc[ia][j][q] = 0.f;

    // per-lane invariant pieces of ldmatrix addresses
    const int arow_lo = (lane & 7) + ((lane >> 3) & 1) * 8;
    const int a_cc_add = (lane >> 4);
    const int brow_lo = (lane & 7) + ((lane >> 4) ? 8 : 0);
    const int b_cc_add = ((lane >> 3) & 1);

    load_chunk_async(0, 0);
    CP_COMMIT();

    for (int c = 0; c < NCHUNK; c++) {
        int s = c & 1;
        if (c + 1 < NCHUNK) {
            load_chunk_async(c + 1, s ^ 1);
            CP_COMMIT();
            CP_WAIT(1);                 // chunk c complete; chunk c+1 in flight
        } else {
            CP_WAIT(0);
        }
        __syncthreads();

        const uint32_t abase = sb + s * 32768;
        const uint32_t bbase = abase + 16384;

        #pragma unroll
        for (int ks = 0; ks < 4; ks++) {
            uint32_t af[2][4], bf[8][2];
            #pragma unroll
            for (int ia = 0; ia < 2; ia++) {
                int row = wm * 32 + ia * 16 + arow_lo;
                uint32_t cc = 2 * ks + a_cc_add;
                uint32_t addr = abase + row * 128 + ((cc << 4) ^ ((row & 7) << 4));
                ldsm4(af[ia][0], af[ia][1], af[ia][2], af[ia][3], addr);
            }
            #pragma unroll
            for (int L = 0; L < 4; L++) {
                int row = wn * 64 + L * 16 + brow_lo;
                uint32_t cc = 2 * ks + b_cc_add;
                uint32_t addr = bbase + row * 128 + ((cc << 4) ^ ((row & 7) << 4));
                ldsm4(bf[2 * L][0], bf[2 * L][1], bf[2 * L + 1][0], bf[2 * L + 1][1], addr);
            }
            #pragma unroll
            for (int ia = 0; ia < 2; ia++)
                #pragma unroll
                for (int j = 0; j < 8; j++)
                    mma16816(acc[ia][j], af[ia], bf[j]);
        }
        __syncthreads();                // stage s safe to overwrite next iteration
    }

    // ---- epilogue: stage 128x128 fp32 in smem (row stride 132), write tile + mirror ----
    float* st = (float*)smem;
    const int g = lane >> 2, q = lane & 3;
    #pragma unroll
    for (int ia = 0; ia < 2; ia++) {
        #pragma unroll
        for (int j = 0; j < 8; j++) {
            int row = wm * 32 + ia * 16 + g;
            int col = wn * 64 + j * 8 + q * 2;
            st[row * 132 + col]           = acc[ia][j][0];
            st[row * 132 + col + 1]       = acc[ia][j][1];
            st[(row + 8) * 132 + col]     = acc[ia][j][2];
            st[(row + 8) * 132 + col + 1] = acc[ia][j][3];
        }
    }
    __syncthreads();

    float* Cb = C + (size_t)b * NN * NN;
    #pragma unroll
    for (int it = 0; it < 16; it++) {
        int idx = tid + 256 * it;
        int row = idx >> 5, cq = idx & 31;
        float4 v = *(float4*)&st[row * 132 + cq * 4];
        *(float4*)&Cb[(size_t)(m0 + row) * NN + n0 + cq * 4] = v;
    }
    if (bx != by) {
        #pragma unroll
        for (int it = 0; it < 16; it++) {
            int idx = tid + 256 * it;
            int row = idx >> 5, cq = idx & 31;
            float4 v;
            v.x = st[(cq * 4 + 0) * 132 + row];
            v.y = st[(cq * 4 + 1) * 132 + row];
            v.z = st[(cq * 4 + 2) * 132 + row];
            v.w = st[(cq * 4 + 3) * 132 + row];
            *(float4*)&Cb[(size_t)(n0 + row) * NN + m0 + cq * 4] = v;
        }
    }
}

// ---------------- 5) per-row: radix-select top-64 + fused sparse-softmax output ----------------
__global__ void __launch_bounds__(256) topk_out_kernel(float* __restrict__ out)
{
    const int n = blockIdx.x;
    const int b = blockIdx.y;
    const int t = threadIdx.x;

    __shared__ int      hist[256];
    __shared__ unsigned sh_prefix;
    __shared__ int      sh_krem;
    __shared__ float    red_f[8];
    __shared__ int      sel_idx[KTOP];
    __shared__ unsigned sel_key[KTOP];
    __shared__ float    sel_w[KTOP];
    __shared__ int      eq_idx[128];
    __shared__ int      cnt_gt, cnt_eq;
    __shared__ float    Zsh;

    const float* row = g_cos + ((size_t)b * NN + n) * NN;

    unsigned kreg[16];
    #pragma unroll
    for (int j = 0; j < 16; j++) {
        unsigned x = __float_as_uint(row[t + 256 * j]);
        kreg[j] = (x & 0x80000000u) ? ~x : (x | 0x80000000u);
    }
    if (t == 0) { sh_prefix = 0u; sh_krem = KTOP; cnt_gt = 0; cnt_eq = 0; }
    __syncthreads();

    // ---- 4-pass 8-bit radix select for the KTOP-th largest key ----
    #pragma unroll
    for (int d = 3; d >= 0; d--) {
        hist[t] = 0;
        __syncthreads();
        const unsigned prefix = sh_prefix;
        const int krem = sh_krem;
        const int shift = d * 8;
        const unsigned mask = (d == 3) ? 0u : (0xFFFFFFFFu << (8 * (d + 1)));
        #pragma unroll
        for (int j = 0; j < 16; j++) {
            unsigned u = kreg[j];
            if ((u & mask) == prefix) atomicAdd(&hist[(u >> shift) & 0xFF], 1);
        }
        __syncthreads();
        if (t < 32) {
            // lane L owns bins [255-8L .. 248-8L] (descending); i=0 highest
            int bins[8];
            int local = 0;
            #pragma unroll
            for (int i2 = 0; i2 < 8; i2++) { bins[i2] = hist[255 - 8 * t - i2]; local += bins[i2]; }
            int excl = local;
            #pragma unroll
            for (int o = 1; o < 32; o <<= 1) {
                int v = __shfl_up_sync(0xffffffffu, excl, o);
                if (t >= o) excl += v;
            }
            excl -= local;                       // sum over lanes with higher bins
            if (excl < krem && krem <= excl + local) {
                int run = excl, digit = 0, gt_before = excl;
                #pragma unroll
                for (int i2 = 0; i2 < 8; i2++) {
                    if (run + bins[i2] >= krem) { digit = 255 - 8 * t - i2; gt_before = run; break; }
                    run += bins[i2];
                }
                sh_prefix = prefix | ((unsigned)digit << shift);
                sh_krem = krem - gt_before;
            }
        }
        __syncthreads();
    }
    const unsigned ustar = sh_prefix;
    const int r = sh_krem;                      // ties at ustar to include

    #pragma unroll
    for (int j = 0; j < 16; j++) {
        unsigned u = kreg[j];
        if (u > ustar) {
            int p = atomicAdd(&cnt_gt, 1);
            sel_idx[p] = t + 256 * j;
            sel_key[p] = u;
        } else if (u == ustar) {
            int p = atomicAdd(&cnt_eq, 1);
            if (p < 128) eq_idx[p] = t + 256 * j;
        }
    }
    __syncthreads();

    const int ngt = cnt_gt;                     // == KTOP - r
    if (t == 0) {
        int ne = cnt_eq < 128 ? cnt_eq : 128;
        for (int a = 1; a < ne; a++) {          // stable: smallest indices first
            int v = eq_idx[a]; int c2 = a - 1;
            while (c2 >= 0 && eq_idx[c2] > v) { eq_idx[c2 + 1] = eq_idx[c2]; c2--; }
            eq_idx[c2 + 1] = v;
        }
        for (int a = 0; a < r; a++) { sel_idx[ngt + a] = eq_idx[a]; sel_key[ngt + a] = ustar; }
    }
    __syncthreads();

    float e_val = 0.f;
    if (t < KTOP) {
        unsigned u = sel_key[t];
        float v = (u & 0x80000000u) ? __uint_as_float(u & 0x7FFFFFFFu) : __uint_as_float(~u);
        e_val = expf(v);
        sel_w[t] = e_val - 1.0f;
    }
    float s = e_val;
    #pragma unroll
    for (int o = 16; o; o >>= 1) s += __shfl_xor_sync(0xffffffffu, s, o);
    if ((t & 31) == 0) red_f[t >> 5] = s;
    __syncthreads();
    if (t == 0) {
        float z = (float)(NN - KTOP);
        #pragma unroll
        for (int w = 0; w < 8; w++) z += red_f[w];
        Zsh = z;
    }
    __syncthreads();

    const float* Vb = g_value + (size_t)b * NN * DD;
    float acc = g_sumv[b * DD + t];
    const float invZ = 1.0f / Zsh;
    #pragma unroll 8
    for (int k = 0; k < KTOP; k++)
        acc += sel_w[k] * Vb[(size_t)sel_idx[k] * DD + t];
    out[((size_t)b * NN + n) * DD + t] = acc * invZ;
}

// ---------------- launch ----------------
extern "C" void kernel_launch(void* const* d_in, const int* in_sizes, int n_in,
                              void* d_out, int out_size)
{
    const float* x    = (const float*)d_in[0];   // [4,4096,256]
    const float* W    = (const float*)d_in[1];   // [256,256]
    const float* bias = (const float*)d_in[2];   // [256]
    float*       out  = (float*)d_out;           // [4,4096,256]

    float *p_value, *p_cos;
    __nv_bfloat16 *p_packA, *p_packB;
    cudaGetSymbolAddress((void**)&p_value, g_value);
    cudaGetSymbolAddress((void**)&p_cos,   g_cos);
    cudaGetSymbolAddress((void**)&p_packA, g_packA);
    cudaGetSymbolAddress((void**)&p_packB, g_packB);

    const int COSMMA_SMEM = 67584;   // max(2*32KB mainloop, 128*132*4 epilogue)
    cudaFuncSetAttribute(cosmma_kernel, cudaFuncAttributeMaxDynamicSharedMemorySize, COSMMA_SMEM);

    // 1) normalize + hi/lo bf16 pack
    normalize_pack_kernel<<<BB * NN, DD>>>(x);

    // 2) value = x @ W^T + b
    sgemm_nt<<<dim3(DD / 128, (BB * NN) / 128, 1), 256>>>(x, W, bias, p_value, BB * NN, DD, DD);

    // 3) per-batch column sums of value
    sumv_part_kernel<<<dim3(16, BB), DD>>>();
    sumv_reduce_kernel<<<BB, DD>>>();

    // 4) cos = packA @ packB^T  (mma.sync bf16, symmetric lower-triangle tiles, cp.async)
    cosmma_kernel<<<dim3((NN / 128) * (NN / 128 + 1) / 2, 1, BB), 256, COSMMA_SMEM>>>(p_packA, p_packB, p_cos);

    // 5) radix-select top-64 + fused sparse softmax output
    topk_out_kernel<<<dim3(NN, BB), 256>>>(out);
}

// round 6
// speedup vs baseline: 3.1058x; 1.0656x over previous
#include <cuda_runtime.h>
#include <cuda_bf16.h>
#include <cstdint>
#include <math.h>

#define BB 4
#define NN 4096
#define DD 256
#define KTOP 64
#define EPSN 1e-12f

#define PACKW 512             // [hi(256) | lo(256)] per row
#define NCHUNK 12             // chunk-pairs realizing [hi|hi|lo]·[hi|lo|hi]

// ---------------- scratch (static device memory; no allocations) ----------------
__device__ float          g_value[(size_t)BB * NN * DD];          // 16 MB
__device__ float          g_cos  [(size_t)BB * NN * NN];          // 256 MB
__device__ __nv_bfloat16  g_pack [(size_t)BB * NN * PACKW];       // 16.8 MB
__device__ __nv_bfloat16  g_Wpack[(size_t)DD * PACKW];            // 0.25 MB
__device__ float          g_norm [(size_t)BB * NN];
__device__ float          g_sumv_part[BB * 16 * DD];
__device__ float          g_sumv[BB * DD];

// chunk-pair remap: A-chunk / B-chunk indices into the [hi(0-3)|lo(4-7)] pack
__device__ __constant__ int CAMAP[NCHUNK] = {0,1,2,3, 0,1,2,3, 4,5,6,7};
__device__ __constant__ int CBMAP[NCHUNK] = {0,1,2,3, 4,5,6,7, 0,1,2,3};

__device__ __forceinline__ uint32_t smem_to_u32(const void* p) {
    uint32_t a;
    asm("{ .reg .u64 t; cvta.to.shared.u64 t, %1; cvt.u32.u64 %0, t; }" : "=r"(a) : "l"(p));
    return a;
}
__device__ __forceinline__ void ldsm4(uint32_t& r0, uint32_t& r1, uint32_t& r2, uint32_t& r3, uint32_t addr) {
    asm volatile("ldmatrix.sync.aligned.m8n8.x4.shared.b16 {%0,%1,%2,%3}, [%4];"
        : "=r"(r0), "=r"(r1), "=r"(r2), "=r"(r3) : "r"(addr));
}
__device__ __forceinline__ void mma16816(float* d, const uint32_t* a, const uint32_t* b) {
    asm volatile("mma.sync.aligned.m16n8k16.row.col.f32.bf16.bf16.f32 "
        "{%0,%1,%2,%3}, {%4,%5,%6,%7}, {%8,%9}, {%0,%1,%2,%3};"
        : "+f"(d[0]), "+f"(d[1]), "+f"(d[2]), "+f"(d[3])
        : "r"(a[0]), "r"(a[1]), "r"(a[2]), "r"(a[3]), "r"(b[0]), "r"(b[1]));
}
__device__ __forceinline__ void cp_async16(uint32_t saddr, const void* gptr) {
    asm volatile("cp.async.cg.shared.global [%0], [%1], 16;" :: "r"(saddr), "l"(gptr) : "memory");
}
#define CP_COMMIT() asm volatile("cp.async.commit_group;" ::: "memory")
#define CP_WAIT(N)  asm volatile("cp.async.wait_group %0;" :: "n"(N) : "memory")

// ---------------- 1) fused row L2-normalize + bf16 hi/lo pack + norm save ----------------
__global__ void __launch_bounds__(DD) normalize_pack_kernel(const float* __restrict__ x)
{
    int row = blockIdx.x;
    int d   = threadIdx.x;
    float v = x[(size_t)row * DD + d];
    float s = v * v;
    __shared__ float red[8];
    #pragma unroll
    for (int o = 16; o; o >>= 1) s += __shfl_xor_sync(0xffffffffu, s, o);
    if ((d & 31) == 0) red[d >> 5] = s;
    __syncthreads();
    if (d < 32) {
        float t = (d < 8) ? red[d] : 0.f;
        #pragma unroll
        for (int o = 4; o; o >>= 1) t += __shfl_xor_sync(0xffffffffu, t, o);
        if (d == 0) red[0] = t;
    }
    __syncthreads();
    float norm = sqrtf(red[0]);
    float nv = v / fmaxf(norm, EPSN);

    __nv_bfloat16 hi = __float2bfloat16(nv);
    __nv_bfloat16 lo = __float2bfloat16(nv - __bfloat162float(hi));

    size_t base = (size_t)row * PACKW;
    g_pack[base + d]       = hi;
    g_pack[base + 256 + d] = lo;
    if (d == 0) g_norm[row] = norm;
}

// ---------------- 1b) W pack: [hi|lo] rows ----------------
__global__ void __launch_bounds__(DD) wpack_kernel(const float* __restrict__ W)
{
    int e = blockIdx.x, d = threadIdx.x;
    float w = W[(size_t)e * DD + d];
    __nv_bfloat16 hi = __float2bfloat16(w);
    __nv_bfloat16 lo = __float2bfloat16(w - __bfloat162float(hi));
    g_Wpack[(size_t)e * PACKW + d]       = hi;
    g_Wpack[(size_t)e * PACKW + 256 + d] = lo;
}

// ---------------- 2) value = norm * (nx @ W^T) + b   (bf16 mma, split-K=768) ----------------
// grid (2, 128): 128x128 tiles over [16384 x 256]. Same mainloop geometry as cosmma.
__global__ void __launch_bounds__(256, 2) valuemma_kernel(const float* __restrict__ bias)
{
    extern __shared__ char smem[];
    const uint32_t sb = smem_to_u32(smem);

    const int tid  = threadIdx.x;
    const int wid  = tid >> 5;
    const int lane = tid & 31;
    const int wm   = wid & 3;
    const int wn   = wid >> 2;
    const int m0   = blockIdx.y * 128;     // global row (over BB*NN)
    const int n0   = blockIdx.x * 128;     // output feature

    const __nv_bfloat16* Agl = g_pack  + (size_t)m0 * PACKW;
    const __nv_bfloat16* Bgl = g_Wpack + (size_t)n0 * PACKW;

    const int lr = tid >> 3;
    const int lj = tid & 7;

    auto load_chunk_async = [&](int c, int s) {
        const char* ga = (const char*)Agl + (size_t)CAMAP[c] * 128;
        const char* gb = (const char*)Bgl + (size_t)CBMAP[c] * 128;
        uint32_t sa = sb + s * 32768;
        uint32_t sbm = sa + 16384;
        #pragma unroll
        for (int k = 0; k < 4; k++) {
            int r = lr + 32 * k;
            uint32_t off = r * 128 + ((lj ^ (r & 7)) << 4);
            cp_async16(sa + off,  ga + (size_t)r * (PACKW * 2) + lj * 16);
            cp_async16(sbm + off, gb + (size_t)r * (PACKW * 2) + lj * 16);
        }
    };

    float acc[2][8][4];
    #pragma unroll
    for (int ia = 0; ia < 2; ia++)
        #pragma unroll
        for (int j = 0; j < 8; j++)
            #pragma unroll
            for (int q = 0; q < 4; q++) acc[ia][j][q] = 0.f;

    const int arow_lo = (lane & 7) + ((lane >> 3) & 1) * 8;
    const int a_cc_add = (lane >> 4);
    const int brow_lo = (lane & 7) + ((lane >> 4) ? 8 : 0);
    const int b_cc_add = ((lane >> 3) & 1);

    load_chunk_async(0, 0);
    CP_COMMIT();

    for (int c = 0; c < NCHUNK; c++) {
        int s = c & 1;
        if (c + 1 < NCHUNK) { load_chunk_async(c + 1, s ^ 1); CP_COMMIT(); CP_WAIT(1); }
        else                { CP_WAIT(0); }
        __syncthreads();

        const uint32_t abase = sb + s * 32768;
        const uint32_t bbase = abase + 16384;

        #pragma unroll
        for (int ks = 0; ks < 4; ks++) {
            uint32_t af[2][4], bf[8][2];
            #pragma unroll
            for (int ia = 0; ia < 2; ia++) {
                int row = wm * 32 + ia * 16 + arow_lo;
                uint32_t cc = 2 * ks + a_cc_add;
                uint32_t addr = abase + row * 128 + ((cc << 4) ^ ((row & 7) << 4));
                ldsm4(af[ia][0], af[ia][1], af[ia][2], af[ia][3], addr);
            }
            #pragma unroll
            for (int L = 0; L < 4; L++) {
                int row = wn * 64 + L * 16 + brow_lo;
                uint32_t cc = 2 * ks + b_cc_add;
                uint32_t addr = bbase + row * 128 + ((cc << 4) ^ ((row & 7) << 4));
                ldsm4(bf[2 * L][0], bf[2 * L][1], bf[2 * L + 1][0], bf[2 * L + 1][1], addr);
            }
            #pragma unroll
            for (int ia = 0; ia < 2; ia++)
                #pragma unroll
                for (int j = 0; j < 8; j++)
                    mma16816(acc[ia][j], af[ia], bf[j]);
        }
        __syncthreads();
    }

    // epilogue: stage, then scaled+biased coalesced store
    float* st = (float*)smem;
    const int g = lane >> 2, q = lane & 3;
    #pragma unroll
    for (int ia = 0; ia < 2; ia++) {
        #pragma unroll
        for (int j = 0; j < 8; j++) {
            int row = wm * 32 + ia * 16 + g;
            int col = wn * 64 + j * 8 + q * 2;
            st[row * 132 + col]           = acc[ia][j][0];
            st[row * 132 + col + 1]       = acc[ia][j][1];
            st[(row + 8) * 132 + col]     = acc[ia][j][2];
            st[(row + 8) * 132 + col + 1] = acc[ia][j][3];
        }
    }
    __syncthreads();

    #pragma unroll
    for (int it = 0; it < 16; it++) {
        int idx = tid + 256 * it;
        int row = idx >> 5, cq = idx & 31;
        float nr = g_norm[m0 + row];
        float4 v = *(float4*)&st[row * 132 + cq * 4];
        int cb = n0 + cq * 4;
        v.x = v.x * nr + __ldg(&bias[cb + 0]);
        v.y = v.y * nr + __ldg(&bias[cb + 1]);
        v.z = v.z * nr + __ldg(&bias[cb + 2]);
        v.w = v.w * nr + __ldg(&bias[cb + 3]);
        *(float4*)&g_value[(size_t)(m0 + row) * DD + cb] = v;
    }
}

// ---------------- 3) column sums of value ----------------
__global__ void __launch_bounds__(DD) sumv_part_kernel()
{
    int b = blockIdx.y, c = blockIdx.x, e = threadIdx.x;
    const float* base = g_value + (size_t)b * NN * DD + (size_t)c * 256 * DD + e;
    float s = 0.f;
    #pragma unroll 8
    for (int n = 0; n < 256; n++) s += base[(size_t)n * DD];
    g_sumv_part[(b * 16 + c) * DD + e] = s;
}
__global__ void __launch_bounds__(DD) sumv_reduce_kernel()
{
    int b = blockIdx.x, e = threadIdx.x;
    float s = 0.f;
    #pragma unroll
    for (int c = 0; c < 16; c++) s += g_sumv_part[(b * 16 + c) * DD + e];
    g_sumv[b * DD + e] = s;
}

// ---------------- 4) bf16 mma.sync GEMM: cos (symmetric lower-triangle, split-K=768) ----------------
__global__ void __launch_bounds__(256, 2) cosmma_kernel(float* __restrict__ C)
{
    extern __shared__ char smem[];
    const uint32_t sb = smem_to_u32(smem);

    const int tid  = threadIdx.x;
    const int wid  = tid >> 5;
    const int lane = tid & 31;
    const int wm   = wid & 3;
    const int wn   = wid >> 2;
    const int b    = blockIdx.z;

    int i  = blockIdx.x;
    int by = (int)((sqrtf(8.f * (float)i + 1.f) - 1.f) * 0.5f);
    while ((by + 1) * (by + 2) / 2 <= i) by++;
    while (by * (by + 1) / 2 > i) by--;
    int bx = i - by * (by + 1) / 2;
    const int m0 = by * 128;
    const int n0 = bx * 128;

    const __nv_bfloat16* Agl = g_pack + ((size_t)b * NN + m0) * PACKW;
    const __nv_bfloat16* Bgl = g_pack + ((size_t)b * NN + n0) * PACKW;

    const int lr = tid >> 3;
    const int lj = tid & 7;

    auto load_chunk_async = [&](int c, int s) {
        const char* ga = (const char*)Agl + (size_t)CAMAP[c] * 128;
        const char* gb = (const char*)Bgl + (size_t)CBMAP[c] * 128;
        uint32_t sa = sb + s * 32768;
        uint32_t sbm = sa + 16384;
        #pragma unroll
        for (int k = 0; k < 4; k++) {
            int r = lr + 32 * k;
            uint32_t off = r * 128 + ((lj ^ (r & 7)) << 4);
            cp_async16(sa + off,  ga + (size_t)r * (PACKW * 2) + lj * 16);
            cp_async16(sbm + off, gb + (size_t)r * (PACKW * 2) + lj * 16);
        }
    };

    float acc[2][8][4];
    #pragma unroll
    for (int ia = 0; ia < 2; ia++)
        #pragma unroll
        for (int j = 0; j < 8; j++)
            #pragma unroll
            for (int q = 0; q < 4; q++) acc[ia][j][q] = 0.f;

    const int arow_lo = (lane & 7) + ((lane >> 3) & 1) * 8;
    const int a_cc_add = (lane >> 4);
    const int brow_lo = (lane & 7) + ((lane >> 4) ? 8 : 0);
    const int b_cc_add = ((lane >> 3) & 1);

    load_chunk_async(0, 0);
    CP_COMMIT();

    for (int c = 0; c < NCHUNK; c++) {
        int s = c & 1;
        if (c + 1 < NCHUNK) { load_chunk_async(c + 1, s ^ 1); CP_COMMIT(); CP_WAIT(1); }
        else                { CP_WAIT(0); }
        __syncthreads();

        const uint32_t abase = sb + s * 32768;
        const uint32_t bbase = abase + 16384;

        #pragma unroll
        for (int ks = 0; ks < 4; ks++) {
            uint32_t af[2][4], bf[8][2];
            #pragma unroll
            for (int ia = 0; ia < 2; ia++) {
                int row = wm * 32 + ia * 16 + arow_lo;
                uint32_t cc = 2 * ks + a_cc_add;
                uint32_t addr = abase + row * 128 + ((cc << 4) ^ ((row & 7) << 4));
                ldsm4(af[ia][0], af[ia][1], af[ia][2], af[ia][3], addr);
            }
            #pragma unroll
            for (int L = 0; L < 4; L++) {
                int row = wn * 64 + L * 16 + brow_lo;
                uint32_t cc = 2 * ks + b_cc_add;
                uint32_t addr = bbase + row * 128 + ((cc << 4) ^ ((row & 7) << 4));
                ldsm4(bf[2 * L][0], bf[2 * L][1], bf[2 * L + 1][0], bf[2 * L + 1][1], addr);
            }
            #pragma unroll
            for (int ia = 0; ia < 2; ia++)
                #pragma unroll
                for (int j = 0; j < 8; j++)
                    mma16816(acc[ia][j], af[ia], bf[j]);
        }
        __syncthreads();
    }

    float* st = (float*)smem;
    const int g = lane >> 2, q = lane & 3;
    #pragma unroll
    for (int ia = 0; ia < 2; ia++) {
        #pragma unroll
        for (int j = 0; j < 8; j++) {
            int row = wm * 32 + ia * 16 + g;
            int col = wn * 64 + j * 8 + q * 2;
            st[row * 132 + col]           = acc[ia][j][0];
            st[row * 132 + col + 1]       = acc[ia][j][1];
            st[(row + 8) * 132 + col]     = acc[ia][j][2];
            st[(row + 8) * 132 + col + 1] = acc[ia][j][3];
        }
    }
    __syncthreads();

    float* Cb = C + (size_t)b * NN * NN;
    #pragma unroll
    for (int it = 0; it < 16; it++) {
        int idx = tid + 256 * it;
        int row = idx >> 5, cq = idx & 31;
        float4 v = *(float4*)&st[row * 132 + cq * 4];
        *(float4*)&Cb[(size_t)(m0 + row) * NN + n0 + cq * 4] = v;
    }
    if (bx != by) {
        #pragma unroll
        for (int it = 0; it < 16; it++) {
            int idx = tid + 256 * it;
            int row = idx >> 5, cq = idx & 31;
            float4 v;
            v.x = st[(cq * 4 + 0) * 132 + row];
            v.y = st[(cq * 4 + 1) * 132 + row];
            v.z = st[(cq * 4 + 2) * 132 + row];
            v.w = st[(cq * 4 + 3) * 132 + row];
            *(float4*)&Cb[(size_t)(n0 + row) * NN + m0 + cq * 4] = v;
        }
    }
}

// ---------------- 5) per-row: radix-select top-64 + fused sparse-softmax output ----------------
__global__ void __launch_bounds__(256) topk_out_kernel(float* __restrict__ out)
{
    const int n = blockIdx.x;
    const int b = blockIdx.y;
    const int t = threadIdx.x;

    __shared__ int      hist[256];
    __shared__ unsigned sh_prefix;
    __shared__ int      sh_krem;
    __shared__ float    red_f[8];
    __shared__ int      sel_idx[KTOP];
    __shared__ unsigned sel_key[KTOP];
    __shared__ float    sel_w[KTOP];
    __shared__ int      eq_idx[128];
    __shared__ int      cnt_gt, cnt_eq;
    __shared__ float    Zsh;

    const float* row = g_cos + ((size_t)b * NN + n) * NN;

    unsigned kreg[16];
    #pragma unroll
    for (int j = 0; j < 16; j++) {
        unsigned x = __float_as_uint(row[t + 256 * j]);
        kreg[j] = (x & 0x80000000u) ? ~x : (x | 0x80000000u);
    }
    if (t == 0) { sh_prefix = 0u; sh_krem = KTOP; cnt_gt = 0; cnt_eq = 0; }
    __syncthreads();

    #pragma unroll
    for (int d = 3; d >= 0; d--) {
        hist[t] = 0;
        __syncthreads();
        const unsigned prefix = sh_prefix;
        const int krem = sh_krem;
        const int shift = d * 8;
        const unsigned mask = (d == 3) ? 0u : (0xFFFFFFFFu << (8 * (d + 1)));
        #pragma unroll
        for (int j = 0; j < 16; j++) {
            unsigned u = kreg[j];
            if ((u & mask) == prefix) atomicAdd(&hist[(u >> shift) & 0xFF], 1);
        }
        __syncthreads();
        if (t < 32) {
            int bins[8];
            int local = 0;
            #pragma unroll
            for (int i2 = 0; i2 < 8; i2++) { bins[i2] = hist[255 - 8 * t - i2]; local += bins[i2]; }
            int excl = local;
            #pragma unroll
            for (int o = 1; o < 32; o <<= 1) {
                int v = __shfl_up_sync(0xffffffffu, excl, o);
                if (t >= o) excl += v;
            }
            excl -= local;
            if (excl < krem && krem <= excl + local) {
                int run = excl, digit = 0, gt_before = excl;
                #pragma unroll
                for (int i2 = 0; i2 < 8; i2++) {
                    if (run + bins[i2] >= krem) { digit = 255 - 8 * t - i2; gt_before = run; break; }
                    run += bins[i2];
                }
                sh_prefix = prefix | ((unsigned)digit << shift);
                sh_krem = krem - gt_before;
            }
        }
        __syncthreads();
    }
    const unsigned ustar = sh_prefix;
    const int r = sh_krem;

    #pragma unroll
    for (int j = 0; j < 16; j++) {
        unsigned u = kreg[j];
        if (u > ustar) {
            int p = atomicAdd(&cnt_gt, 1);
            sel_idx[p] = t + 256 * j;
            sel_key[p] = u;
        } else if (u == ustar) {
            int p = atomicAdd(&cnt_eq, 1);
            if (p < 128) eq_idx[p] = t + 256 * j;
        }
    }
    __syncthreads();

    const int ngt = cnt_gt;
    if (t == 0) {
        int ne = cnt_eq < 128 ? cnt_eq : 128;
        for (int a = 1; a < ne; a++) {
            int v = eq_idx[a]; int c2 = a - 1;
            while (c2 >= 0 && eq_idx[c2] > v) { eq_idx[c2 + 1] = eq_idx[c2]; c2--; }
            eq_idx[c2 + 1] = v;
        }
        for (int a = 0; a < r; a++) { sel_idx[ngt + a] = eq_idx[a]; sel_key[ngt + a] = ustar; }
    }
    __syncthreads();

    float e_val = 0.f;
    if (t < KTOP) {
        unsigned u = sel_key[t];
        float v = (u & 0x80000000u) ? __uint_as_float(u & 0x7FFFFFFFu) : __uint_as_float(~u);
        e_val = expf(v);
        sel_w[t] = e_val - 1.0f;
    }
    float s = e_val;
    #pragma unroll
    for (int o = 16; o; o >>= 1) s += __shfl_xor_sync(0xffffffffu, s, o);
    if ((t & 31) == 0) red_f[t >> 5] = s;
    __syncthreads();
    if (t == 0) {
        float z = (float)(NN - KTOP);
        #pragma unroll
        for (int w = 0; w < 8; w++) z += red_f[w];
        Zsh = z;
    }
    __syncthreads();

    const float* Vb = g_value + (size_t)b * NN * DD;
    float acc = g_sumv[b * DD + t];
    const float invZ = 1.0f / Zsh;
    #pragma unroll 8
    for (int k = 0; k < KTOP; k++)
        acc += sel_w[k] * Vb[(size_t)sel_idx[k] * DD + t];
    out[((size_t)b * NN + n) * DD + t] = acc * invZ;
}

// ---------------- launch ----------------
extern "C" void kernel_launch(void* const* d_in, const int* in_sizes, int n_in,
                              void* d_out, int out_size)
{
    const float* x    = (const float*)d_in[0];   // [4,4096,256]
    const float* W    = (const float*)d_in[1];   // [256,256]
    const float* bias = (const float*)d_in[2];   // [256]
    float*       out  = (float*)d_out;           // [4,4096,256]

    float* p_cos;
    cudaGetSymbolAddress((void**)&p_cos, g_cos);

    const int MMA_SMEM = 67584;   // max(2*32KB mainloop, 128*132*4 epilogue)
    cudaFuncSetAttribute(cosmma_kernel,   cudaFuncAttributeMaxDynamicSharedMemorySize, MMA_SMEM);
    cudaFuncSetAttribute(valuemma_kernel, cudaFuncAttributeMaxDynamicSharedMemorySize, MMA_SMEM);

    // 1) normalize + hi/lo pack + norms         (launch #1)
    normalize_pack_kernel<<<BB * NN, DD>>>(x);
    // 1b) W pack                                 (launch #2)
    wpack_kernel<<<DD, DD>>>(W);
    // 2) value via bf16 mma + norm rescale       (launch #3)
    valuemma_kernel<<<dim3(DD / 128, (BB * NN) / 128), 256, MMA_SMEM>>>(bias);
    // 4) cos GEMM (position 4 for the profiler)  (launch #4)
    cosmma_kernel<<<dim3((NN / 128) * (NN / 128 + 1) / 2, 1, BB), 256, MMA_SMEM>>>(p_cos);
    // 3) column sums of value                    (launches #5, #6)
    sumv_part_kernel<<<dim3(16, BB), DD>>>();
    sumv_reduce_kernel<<<BB, DD>>>();
    // 5) radix top-64 + fused output             (launch #7)
    topk_out_kernel<<<dim3(NN, BB), 256>>>(out);
}

// round 7
// speedup vs baseline: 3.3903x; 1.0916x over previous
#include <cuda_runtime.h>
#include <cuda_bf16.h>
#include <cstdint>
#include <math.h>

#define BB 4
#define NN 4096
#define DD 256
#define KTOP 64
#define EPSN 1e-12f

#define PACKW 512             // [hi(256) | lo(256)] per row
#define NCHUNK_V 12           // value: [hi|hi|lo]·[hi|lo|hi]  (full split, error ~1e-7)
#define NCHUNK_C 8            // cos:   H·(H+L)^T              (drops L·H^T, error ~1e-4 in cos -> ~1e-5 in out)

// ---------------- scratch (static device memory; no allocations) ----------------
__device__ float          g_value[(size_t)BB * NN * DD];          // 16 MB
__device__ float          g_cos  [(size_t)BB * NN * NN];          // 256 MB
__device__ __nv_bfloat16  g_pack [(size_t)BB * NN * PACKW];       // 16.8 MB
__device__ __nv_bfloat16  g_Wpack[(size_t)DD * PACKW];            // 0.25 MB
__device__ float          g_norm [(size_t)BB * NN];
__device__ float          g_sumv_part[BB * 16 * DD];
__device__ float          g_sumv[BB * DD];

// chunk-pair remap for the value GEMM (full 3-term split)
__device__ __constant__ int CAMAP_V[NCHUNK_V] = {0,1,2,3, 0,1,2,3, 4,5,6,7};
__device__ __constant__ int CBMAP_V[NCHUNK_V] = {0,1,2,3, 4,5,6,7, 0,1,2,3};

__device__ __forceinline__ uint32_t smem_to_u32(const void* p) {
    uint32_t a;
    asm("{ .reg .u64 t; cvta.to.shared.u64 t, %1; cvt.u32.u64 %0, t; }" : "=r"(a) : "l"(p));
    return a;
}
__device__ __forceinline__ void ldsm4(uint32_t& r0, uint32_t& r1, uint32_t& r2, uint32_t& r3, uint32_t addr) {
    asm volatile("ldmatrix.sync.aligned.m8n8.x4.shared.b16 {%0,%1,%2,%3}, [%4];"
        : "=r"(r0), "=r"(r1), "=r"(r2), "=r"(r3) : "r"(addr));
}
__device__ __forceinline__ void mma16816(float* d, const uint32_t* a, const uint32_t* b) {
    asm volatile("mma.sync.aligned.m16n8k16.row.col.f32.bf16.bf16.f32 "
        "{%0,%1,%2,%3}, {%4,%5,%6,%7}, {%8,%9}, {%0,%1,%2,%3};"
        : "+f"(d[0]), "+f"(d[1]), "+f"(d[2]), "+f"(d[3])
        : "r"(a[0]), "r"(a[1]), "r"(a[2]), "r"(a[3]), "r"(b[0]), "r"(b[1]));
}
__device__ __forceinline__ void cp_async16(uint32_t saddr, const void* gptr) {
    asm volatile("cp.async.cg.shared.global [%0], [%1], 16;" :: "r"(saddr), "l"(gptr) : "memory");
}
#define CP_COMMIT() asm volatile("cp.async.commit_group;" ::: "memory")
#define CP_WAIT(N)  asm volatile("cp.async.wait_group %0;" :: "n"(N) : "memory")

// ---------------- 1) fused row L2-normalize + bf16 hi/lo pack + norm save ----------------
__global__ void __launch_bounds__(DD) normalize_pack_kernel(const float* __restrict__ x)
{
    int row = blockIdx.x;
    int d   = threadIdx.x;
    float v = x[(size_t)row * DD + d];
    float s = v * v;
    __shared__ float red[8];
    #pragma unroll
    for (int o = 16; o; o >>= 1) s += __shfl_xor_sync(0xffffffffu, s, o);
    if ((d & 31) == 0) red[d >> 5] = s;
    __syncthreads();
    if (d < 32) {
        float t = (d < 8) ? red[d] : 0.f;
        #pragma unroll
        for (int o = 4; o; o >>= 1) t += __shfl_xor_sync(0xffffffffu, t, o);
        if (d == 0) red[0] = t;
    }
    __syncthreads();
    float norm = sqrtf(red[0]);
    float nv = v / fmaxf(norm, EPSN);

    __nv_bfloat16 hi = __float2bfloat16(nv);
    __nv_bfloat16 lo = __float2bfloat16(nv - __bfloat162float(hi));

    size_t base = (size_t)row * PACKW;
    g_pack[base + d]       = hi;
    g_pack[base + 256 + d] = lo;
    if (d == 0) g_norm[row] = norm;
}

// ---------------- 1b) W pack: [hi|lo] rows ----------------
__global__ void __launch_bounds__(DD) wpack_kernel(const float* __restrict__ W)
{
    int e = blockIdx.x, d = threadIdx.x;
    float w = W[(size_t)e * DD + d];
    __nv_bfloat16 hi = __float2bfloat16(w);
    __nv_bfloat16 lo = __float2bfloat16(w - __bfloat162float(hi));
    g_Wpack[(size_t)e * PACKW + d]       = hi;
    g_Wpack[(size_t)e * PACKW + 256 + d] = lo;
}

// ---------------- 2) value = norm * (nx @ W^T) + b   (bf16 mma, 3-term split) ----------------
__global__ void __launch_bounds__(256, 2) valuemma_kernel(const float* __restrict__ bias)
{
    extern __shared__ char smem[];
    const uint32_t sb = smem_to_u32(smem);

    const int tid  = threadIdx.x;
    const int wid  = tid >> 5;
    const int lane = tid & 31;
    const int wm   = wid & 3;
    const int wn   = wid >> 2;
    const int m0   = blockIdx.y * 128;
    const int n0   = blockIdx.x * 128;

    const __nv_bfloat16* Agl = g_pack  + (size_t)m0 * PACKW;
    const __nv_bfloat16* Bgl = g_Wpack + (size_t)n0 * PACKW;

    const int lr = tid >> 3;
    const int lj = tid & 7;

    auto load_chunk_async = [&](int c, int s) {
        const char* ga = (const char*)Agl + (size_t)CAMAP_V[c] * 128;
        const char* gb = (const char*)Bgl + (size_t)CBMAP_V[c] * 128;
        uint32_t sa = sb + s * 32768;
        uint32_t sbm = sa + 16384;
        #pragma unroll
        for (int k = 0; k < 4; k++) {
            int r = lr + 32 * k;
            uint32_t off = r * 128 + ((lj ^ (r & 7)) << 4);
            cp_async16(sa + off,  ga + (size_t)r * (PACKW * 2) + lj * 16);
            cp_async16(sbm + off, gb + (size_t)r * (PACKW * 2) + lj * 16);
        }
    };

    float acc[2][8][4];
    #pragma unroll
    for (int ia = 0; ia < 2; ia++)
        #pragma unroll
        for (int j = 0; j < 8; j++)
            #pragma unroll
            for (int q = 0; q < 4; q++) acc[ia][j][q] = 0.f;

    const int arow_lo = (lane & 7) + ((lane >> 3) & 1) * 8;
    const int a_cc_add = (lane >> 4);
    const int brow_lo = (lane & 7) + ((lane >> 4) ? 8 : 0);
    const int b_cc_add = ((lane >> 3) & 1);

    load_chunk_async(0, 0);
    CP_COMMIT();

    for (int c = 0; c < NCHUNK_V; c++) {
        int s = c & 1;
        if (c + 1 < NCHUNK_V) { load_chunk_async(c + 1, s ^ 1); CP_COMMIT(); CP_WAIT(1); }
        else                  { CP_WAIT(0); }
        __syncthreads();

        const uint32_t abase = sb + s * 32768;
        const uint32_t bbase = abase + 16384;

        #pragma unroll
        for (int ks = 0; ks < 4; ks++) {
            uint32_t af[2][4], bf[8][2];
            #pragma unroll
            for (int ia = 0; ia < 2; ia++) {
                int row = wm * 32 + ia * 16 + arow_lo;
                uint32_t cc = 2 * ks + a_cc_add;
                uint32_t addr = abase + row * 128 + ((cc << 4) ^ ((row & 7) << 4));
                ldsm4(af[ia][0], af[ia][1], af[ia][2], af[ia][3], addr);
            }
            #pragma unroll
            for (int L = 0; L < 4; L++) {
                int row = wn * 64 + L * 16 + brow_lo;
                uint32_t cc = 2 * ks + b_cc_add;
                uint32_t addr = bbase + row * 128 + ((cc << 4) ^ ((row & 7) << 4));
                ldsm4(bf[2 * L][0], bf[2 * L][1], bf[2 * L + 1][0], bf[2 * L + 1][1], addr);
            }
            #pragma unroll
            for (int ia = 0; ia < 2; ia++)
                #pragma unroll
                for (int j = 0; j < 8; j++)
                    mma16816(acc[ia][j], af[ia], bf[j]);
        }
        __syncthreads();
    }

    float* st = (float*)smem;
    const int g = lane >> 2, q = lane & 3;
    #pragma unroll
    for (int ia = 0; ia < 2; ia++) {
        #pragma unroll
        for (int j = 0; j < 8; j++) {
            int row = wm * 32 + ia * 16 + g;
            int col = wn * 64 + j * 8 + q * 2;
            st[row * 132 + col]           = acc[ia][j][0];
            st[row * 132 + col + 1]       = acc[ia][j][1];
            st[(row + 8) * 132 + col]     = acc[ia][j][2];
            st[(row + 8) * 132 + col + 1] = acc[ia][j][3];
        }
    }
    __syncthreads();

    #pragma unroll
    for (int it = 0; it < 16; it++) {
        int idx = tid + 256 * it;
        int row = idx >> 5, cq = idx & 31;
        float nr = g_norm[m0 + row];
        float4 v = *(float4*)&st[row * 132 + cq * 4];
        int cb = n0 + cq * 4;
        v.x = v.x * nr + __ldg(&bias[cb + 0]);
        v.y = v.y * nr + __ldg(&bias[cb + 1]);
        v.z = v.z * nr + __ldg(&bias[cb + 2]);
        v.w = v.w * nr + __ldg(&bias[cb + 3]);
        *(float4*)&g_value[(size_t)(m0 + row) * DD + cb] = v;
    }
}

// ---------------- 3) column sums of value ----------------
__global__ void __launch_bounds__(DD) sumv_part_kernel()
{
    int b = blockIdx.y, c = blockIdx.x, e = threadIdx.x;
    const float* base = g_value + (size_t)b * NN * DD + (size_t)c * 256 * DD + e;
    float s = 0.f;
    #pragma unroll 8
    for (int n = 0; n < 256; n++) s += base[(size_t)n * DD];
    g_sumv_part[(b * 16 + c) * DD + e] = s;
}
__global__ void __launch_bounds__(DD) sumv_reduce_kernel()
{
    int b = blockIdx.x, e = threadIdx.x;
    float s = 0.f;
    #pragma unroll
    for (int c = 0; c < 16; c++) s += g_sumv_part[(b * 16 + c) * DD + e];
    g_sumv[b * DD + e] = s;
}

// ---------------- 4) bf16 mma.sync GEMM: cos = H @ (H+L)^T  (8 chunk-pairs) ----------------
// A uses hi chunks only (c & 3); B uses hi (c<4) then lo (c>=4).
__global__ void __launch_bounds__(256, 2) cosmma_kernel(float* __restrict__ C)
{
    extern __shared__ char smem[];
    const uint32_t sb = smem_to_u32(smem);

    const int tid  = threadIdx.x;
    const int wid  = tid >> 5;
    const int lane = tid & 31;
    const int wm   = wid & 3;
    const int wn   = wid >> 2;
    const int b    = blockIdx.z;

    int i  = blockIdx.x;
    int by = (int)((sqrtf(8.f * (float)i + 1.f) - 1.f) * 0.5f);
    while ((by + 1) * (by + 2) / 2 <= i) by++;
    while (by * (by + 1) / 2 > i) by--;
    int bx = i - by * (by + 1) / 2;
    const int m0 = by * 128;
    const int n0 = bx * 128;

    const __nv_bfloat16* Agl = g_pack + ((size_t)b * NN + m0) * PACKW;
    const __nv_bfloat16* Bgl = g_pack + ((size_t)b * NN + n0) * PACKW;

    const int lr = tid >> 3;
    const int lj = tid & 7;

    auto load_chunk_async = [&](int c, int s) {
        const char* ga = (const char*)Agl + (size_t)(c & 3) * 128;   // hi only
        const char* gb = (const char*)Bgl + (size_t)c * 128;         // hi then lo
        uint32_t sa = sb + s * 32768;
        uint32_t sbm = sa + 16384;
        #pragma unroll
        for (int k = 0; k < 4; k++) {
            int r = lr + 32 * k;
            uint32_t off = r * 128 + ((lj ^ (r & 7)) << 4);
            cp_async16(sa + off,  ga + (size_t)r * (PACKW * 2) + lj * 16);
            cp_async16(sbm + off, gb + (size_t)r * (PACKW * 2) + lj * 16);
        }
    };

    float acc[2][8][4];
    #pragma unroll
    for (int ia = 0; ia < 2; ia++)
        #pragma unroll
        for (int j = 0; j < 8; j++)
            #pragma unroll
            for (int q = 0; q < 4; q++) acc[ia][j][q] = 0.f;

    const int arow_lo = (lane & 7) + ((lane >> 3) & 1) * 8;
    const int a_cc_add = (lane >> 4);
    const int brow_lo = (lane & 7) + ((lane >> 4) ? 8 : 0);
    const int b_cc_add = ((lane >> 3) & 1);

    load_chunk_async(0, 0);
    CP_COMMIT();

    for (int c = 0; c < NCHUNK_C; c++) {
        int s = c & 1;
        if (c + 1 < NCHUNK_C) { load_chunk_async(c + 1, s ^ 1); CP_COMMIT(); CP_WAIT(1); }
        else                  { CP_WAIT(0); }
        __syncthreads();

        const uint32_t abase = sb + s * 32768;
        const uint32_t bbase = abase + 16384;

        #pragma unroll
        for (int ks = 0; ks < 4; ks++) {
            uint32_t af[2][4], bf[8][2];
            #pragma unroll
            for (int ia = 0; ia < 2; ia++) {
                int row = wm * 32 + ia * 16 + arow_lo;
                uint32_t cc = 2 * ks + a_cc_add;
                uint32_t addr = abase + row * 128 + ((cc << 4) ^ ((row & 7) << 4));
                ldsm4(af[ia][0], af[ia][1], af[ia][2], af[ia][3], addr);
            }
            #pragma unroll
            for (int L = 0; L < 4; L++) {
                int row = wn * 64 + L * 16 + brow_lo;
                uint32_t cc = 2 * ks + b_cc_add;
                uint32_t addr = bbase + row * 128 + ((cc << 4) ^ ((row & 7) << 4));
                ldsm4(bf[2 * L][0], bf[2 * L][1], bf[2 * L + 1][0], bf[2 * L + 1][1], addr);
            }
            #pragma unroll
            for (int ia = 0; ia < 2; ia++)
                #pragma unroll
                for (int j = 0; j < 8; j++)
                    mma16816(acc[ia][j], af[ia], bf[j]);
        }
        __syncthreads();
    }

    float* st = (float*)smem;
    const int g = lane >> 2, q = lane & 3;
    #pragma unroll
    for (int ia = 0; ia < 2; ia++) {
        #pragma unroll
        for (int j = 0; j < 8; j++) {
            int row = wm * 32 + ia * 16 + g;
            int col = wn * 64 + j * 8 + q * 2;
            st[row * 132 + col]           = acc[ia][j][0];
            st[row * 132 + col + 1]       = acc[ia][j][1];
            st[(row + 8) * 132 + col]     = acc[ia][j][2];
            st[(row + 8) * 132 + col + 1] = acc[ia][j][3];
        }
    }
    __syncthreads();

    float* Cb = C + (size_t)b * NN * NN;
    #pragma unroll
    for (int it = 0; it < 16; it++) {
        int idx = tid + 256 * it;
        int row = idx >> 5, cq = idx & 31;
        float4 v = *(float4*)&st[row * 132 + cq * 4];
        *(float4*)&Cb[(size_t)(m0 + row) * NN + n0 + cq * 4] = v;
    }
    if (bx != by) {
        #pragma unroll
        for (int it = 0; it < 16; it++) {
            int idx = tid + 256 * it;
            int row = idx >> 5, cq = idx & 31;
            float4 v;
            v.x = st[(cq * 4 + 0) * 132 + row];
            v.y = st[(cq * 4 + 1) * 132 + row];
            v.z = st[(cq * 4 + 2) * 132 + row];
            v.w = st[(cq * 4 + 3) * 132 + row];
            *(float4*)&Cb[(size_t)(n0 + row) * NN + m0 + cq * 4] = v;
        }
    }
}

// ---------------- 5) per-row: radix-select top-64 + fused sparse-softmax output ----------------
__global__ void __launch_bounds__(256) topk_out_kernel(float* __restrict__ out)
{
    const int n = blockIdx.x;
    const int b = blockIdx.y;
    const int t = threadIdx.x;

    __shared__ int      hist[256];
    __shared__ unsigned sh_prefix;
    __shared__ int      sh_krem;
    __shared__ float    red_f[8];
    __shared__ int      sel_idx[KTOP];
    __shared__ unsigned sel_key[KTOP];
    __shared__ float    sel_w[KTOP];
    __shared__ int      eq_idx[128];
    __shared__ int      cnt_gt, cnt_eq;
    __shared__ float    Zsh;

    const float* row = g_cos + ((size_t)b * NN + n) * NN;

    // float4 row load; kreg[4*j+q] corresponds to index 1024*j + 4*t + q
    unsigned kreg[16];
    #pragma unroll
    for (int j = 0; j < 4; j++) {
        float4 v = *(const float4*)&row[1024 * j + 4 * t];
        const float vv[4] = {v.x, v.y, v.z, v.w};
        #pragma unroll
        for (int q = 0; q < 4; q++) {
            unsigned x = __float_as_uint(vv[q]);
            kreg[4 * j + q] = (x & 0x80000000u) ? ~x : (x | 0x80000000u);
        }
    }
    if (t == 0) { sh_prefix = 0u; sh_krem = KTOP; cnt_gt = 0; cnt_eq = 0; }
    __syncthreads();

    #pragma unroll
    for (int d = 3; d >= 0; d--) {
        hist[t] = 0;
        __syncthreads();
        const unsigned prefix = sh_prefix;
        const int krem = sh_krem;
        const int shift = d * 8;
        const unsigned mask = (d == 3) ? 0u : (0xFFFFFFFFu << (8 * (d + 1)));
        #pragma unroll
        for (int j = 0; j < 16; j++) {
            unsigned u = kreg[j];
            if ((u & mask) == prefix) atomicAdd(&hist[(u >> shift) & 0xFF], 1);
        }
        __syncthreads();
        if (t < 32) {
            int bins[8];
            int local = 0;
            #pragma unroll
            for (int i2 = 0; i2 < 8; i2++) { bins[i2] = hist[255 - 8 * t - i2]; local += bins[i2]; }
            int excl = local;
            #pragma unroll
            for (int o = 1; o < 32; o <<= 1) {
                int v = __shfl_up_sync(0xffffffffu, excl, o);
                if (t >= o) excl += v;
            }
            excl -= local;
            if (excl < krem && krem <= excl + local) {
                int run = excl, digit = 0, gt_before = excl;
                #pragma unroll
                for (int i2 = 0; i2 < 8; i2++) {
                    if (run + bins[i2] >= krem) { digit = 255 - 8 * t - i2; gt_before = run; break; }
                    run += bins[i2];
                }
                sh_prefix = prefix | ((unsigned)digit << shift);
                sh_krem = krem - gt_before;
            }
        }
        __syncthreads();
    }
    const unsigned ustar = sh_prefix;
    const int r = sh_krem;

    #pragma unroll
    for (int j = 0; j < 16; j++) {
        unsigned u = kreg[j];
        int idx = ((j >> 2) << 10) + (t << 2) + (j & 3);
        if (u > ustar) {
            int p = atomicAdd(&cnt_gt, 1);
            sel_idx[p] = idx;
            sel_key[p] = u;
        } else if (u == ustar) {
            int p = atomicAdd(&cnt_eq, 1);
            if (p < 128) eq_idx[p] = idx;
        }
    }
    __syncthreads();

    const int ngt = cnt_gt;
    if (t == 0) {
        int ne = cnt_eq < 128 ? cnt_eq : 128;
        for (int a = 1; a < ne; a++) {
            int v = eq_idx[a]; int c2 = a - 1;
            while (c2 >= 0 && eq_idx[c2] > v) { eq_idx[c2 + 1] = eq_idx[c2]; c2--; }
            eq_idx[c2 + 1] = v;
        }
        for (int a = 0; a < r; a++) { sel_idx[ngt + a] = eq_idx[a]; sel_key[ngt + a] = ustar; }
    }
    __syncthreads();

    float e_val = 0.f;
    if (t < KTOP) {
        unsigned u = sel_key[t];
        float v = (u & 0x80000000u) ? __uint_as_float(u & 0x7FFFFFFFu) : __uint_as_float(~u);
        e_val = expf(v);
        sel_w[t] = e_val - 1.0f;
    }
    float s = e_val;
    #pragma unroll
    for (int o = 16; o; o >>= 1) s += __shfl_xor_sync(0xffffffffu, s, o);
    if ((t & 31) == 0) red_f[t >> 5] = s;
    __syncthreads();
    if (t == 0) {
        float z = (float)(NN - KTOP);
        #pragma unroll
        for (int w = 0; w < 8; w++) z += red_f[w];
        Zsh = z;
    }
    __syncthreads();

    const float* Vb = g_value + (size_t)b * NN * DD;
    float acc = g_sumv[b * DD + t];
    const float invZ = 1.0f / Zsh;
    #pragma unroll 8
    for (int k = 0; k < KTOP; k++)
        acc += sel_w[k] * Vb[(size_t)sel_idx[k] * DD + t];
    out[((size_t)b * NN + n) * DD + t] = acc * invZ;
}

// ---------------- launch ----------------
extern "C" void kernel_launch(void* const* d_in, const int* in_sizes, int n_in,
                              void* d_out, int out_size)
{
    const float* x    = (const float*)d_in[0];   // [4,4096,256]
    const float* W    = (const float*)d_in[1];   // [256,256]
    const float* bias = (const float*)d_in[2];   // [256]
    float*       out  = (float*)d_out;           // [4,4096,256]

    float* p_cos;
    cudaGetSymbolAddress((void**)&p_cos, g_cos);

    const int MMA_SMEM = 67584;
    cudaFuncSetAttribute(cosmma_kernel,   cudaFuncAttributeMaxDynamicSharedMemorySize, MMA_SMEM);
    cudaFuncSetAttribute(valuemma_kernel, cudaFuncAttributeMaxDynamicSharedMemorySize, MMA_SMEM);

    // 1) normalize + hi/lo pack + norms         (launch #1)
    normalize_pack_kernel<<<BB * NN, DD>>>(x);
    // 1b) W pack                                 (launch #2)
    wpack_kernel<<<DD, DD>>>(W);
    // 2) value via bf16 mma + norm rescale       (launch #3)
    valuemma_kernel<<<dim3(DD / 128, (BB * NN) / 128), 256, MMA_SMEM>>>(bias);
    // 4) cos GEMM (position 4 for the profiler)  (launch #4)
    cosmma_kernel<<<dim3((NN / 128) * (NN / 128 + 1) / 2, 1, BB), 256, MMA_SMEM>>>(p_cos);
    // 3) column sums of value                    (launches #5, #6)
    sumv_part_kernel<<<dim3(16, BB), DD>>>();
    sumv_reduce_kernel<<<BB, DD>>>();
    // 5) radix top-64 + fused output             (launch #7)
    topk_out_kernel<<<dim3(NN, BB), 256>>>(out);
}

// round 8
// speedup vs baseline: 3.9550x; 1.1666x over previous
#include <cuda_runtime.h>
#include <cuda_bf16.h>
#include <cstdint>
#include <math.h>

#define BB 4
#define NN 4096
#define DD 256
#define KTOP 64
#define EPSN 1e-12f

#define PACKW 512             // [hi(256) | lo(256)] per row
#define NCHUNK_V 12           // value: full 3-term split (error ~1e-7)
#define NCHUNK_C 8            // cos: H·(H+L)^T (drops L·H^T)

// ---------------- scratch ----------------
__device__ float          g_value[(size_t)BB * NN * DD];
__device__ float          g_cos  [(size_t)BB * NN * NN];
__device__ __nv_bfloat16  g_pack [(size_t)BB * NN * PACKW];
__device__ __nv_bfloat16  g_Wpack[(size_t)DD * PACKW];
__device__ float          g_norm [(size_t)BB * NN];
__device__ float          g_sumv_part[BB * 16 * DD];
__device__ float          g_sumv[BB * DD];

__device__ __constant__ int CAMAP_V[NCHUNK_V] = {0,1,2,3, 0,1,2,3, 4,5,6,7};
__device__ __constant__ int CBMAP_V[NCHUNK_V] = {0,1,2,3, 4,5,6,7, 0,1,2,3};

__device__ __forceinline__ uint32_t smem_to_u32(const void* p) {
    uint32_t a;
    asm("{ .reg .u64 t; cvta.to.shared.u64 t, %1; cvt.u32.u64 %0, t; }" : "=r"(a) : "l"(p));
    return a;
}
__device__ __forceinline__ void ldsm4(uint32_t& r0, uint32_t& r1, uint32_t& r2, uint32_t& r3, uint32_t addr) {
    asm volatile("ldmatrix.sync.aligned.m8n8.x4.shared.b16 {%0,%1,%2,%3}, [%4];"
        : "=r"(r0), "=r"(r1), "=r"(r2), "=r"(r3) : "r"(addr));
}
__device__ __forceinline__ void mma16816(float* d, const uint32_t* a, const uint32_t* b) {
    asm volatile("mma.sync.aligned.m16n8k16.row.col.f32.bf16.bf16.f32 "
        "{%0,%1,%2,%3}, {%4,%5,%6,%7}, {%8,%9}, {%0,%1,%2,%3};"
        : "+f"(d[0]), "+f"(d[1]), "+f"(d[2]), "+f"(d[3])
        : "r"(a[0]), "r"(a[1]), "r"(a[2]), "r"(a[3]), "r"(b[0]), "r"(b[1]));
}
__device__ __forceinline__ void cp_async16(uint32_t saddr, const void* gptr) {
    asm volatile("cp.async.cg.shared.global [%0], [%1], 16;" :: "r"(saddr), "l"(gptr) : "memory");
}
#define CP_COMMIT() asm volatile("cp.async.commit_group;" ::: "memory")
#define CP_WAIT(N)  asm volatile("cp.async.wait_group %0;" :: "n"(N) : "memory")

// ---------------- 1) normalize + hi/lo pack + norm save ----------------
__global__ void __launch_bounds__(DD) normalize_pack_kernel(const float* __restrict__ x)
{
    int row = blockIdx.x;
    int d   = threadIdx.x;
    float v = x[(size_t)row * DD + d];
    float s = v * v;
    __shared__ float red[8];
    #pragma unroll
    for (int o = 16; o; o >>= 1) s += __shfl_xor_sync(0xffffffffu, s, o);
    if ((d & 31) == 0) red[d >> 5] = s;
    __syncthreads();
    if (d < 32) {
        float t = (d < 8) ? red[d] : 0.f;
        #pragma unroll
        for (int o = 4; o; o >>= 1) t += __shfl_xor_sync(0xffffffffu, t, o);
        if (d == 0) red[0] = t;
    }
    __syncthreads();
    float norm = sqrtf(red[0]);
    float nv = v / fmaxf(norm, EPSN);

    __nv_bfloat16 hi = __float2bfloat16(nv);
    __nv_bfloat16 lo = __float2bfloat16(nv - __bfloat162float(hi));

    size_t base = (size_t)row * PACKW;
    g_pack[base + d]       = hi;
    g_pack[base + 256 + d] = lo;
    if (d == 0) g_norm[row] = norm;
}

// ---------------- 1b) W pack ----------------
__global__ void __launch_bounds__(DD) wpack_kernel(const float* __restrict__ W)
{
    int e = blockIdx.x, d = threadIdx.x;
    float w = W[(size_t)e * DD + d];
    __nv_bfloat16 hi = __float2bfloat16(w);
    __nv_bfloat16 lo = __float2bfloat16(w - __bfloat162float(hi));
    g_Wpack[(size_t)e * PACKW + d]       = hi;
    g_Wpack[(size_t)e * PACKW + 256 + d] = lo;
}

// ---------------- 2) value = norm * (nx @ W^T) + b  (bf16 mma, 3-stage pipe) ----------------
__global__ void __launch_bounds__(256, 2) valuemma_kernel(const float* __restrict__ bias)
{
    extern __shared__ char smem[];
    const uint32_t sb = smem_to_u32(smem);

    const int tid  = threadIdx.x;
    const int wid  = tid >> 5;
    const int lane = tid & 31;
    const int wm   = wid & 3;
    const int wn   = wid >> 2;
    const int m0   = blockIdx.y * 128;
    const int n0   = blockIdx.x * 128;

    const __nv_bfloat16* Agl = g_pack  + (size_t)m0 * PACKW;
    const __nv_bfloat16* Bgl = g_Wpack + (size_t)n0 * PACKW;

    const int lr = tid >> 3;
    const int lj = tid & 7;

    auto load_chunk_async = [&](int c, int s) {
        const char* ga = (const char*)Agl + (size_t)CAMAP_V[c] * 128;
        const char* gb = (const char*)Bgl + (size_t)CBMAP_V[c] * 128;
        uint32_t sa = sb + s * 32768;
        uint32_t sbm = sa + 16384;
        #pragma unroll
        for (int k = 0; k < 4; k++) {
            int r = lr + 32 * k;
            uint32_t off = r * 128 + ((lj ^ (r & 7)) << 4);
            cp_async16(sa + off,  ga + (size_t)r * (PACKW * 2) + lj * 16);
            cp_async16(sbm + off, gb + (size_t)r * (PACKW * 2) + lj * 16);
        }
    };

    float acc[2][8][4];
    #pragma unroll
    for (int ia = 0; ia < 2; ia++)
        #pragma unroll
        for (int j = 0; j < 8; j++)
            #pragma unroll
            for (int q = 0; q < 4; q++) acc[ia][j][q] = 0.f;

    const int arow_lo = (lane & 7) + ((lane >> 3) & 1) * 8;
    const int a_cc_add = (lane >> 4);
    const int brow_lo = (lane & 7) + ((lane >> 4) ? 8 : 0);
    const int b_cc_add = ((lane >> 3) & 1);

    load_chunk_async(0, 0); CP_COMMIT();
    load_chunk_async(1, 1); CP_COMMIT();

    for (int c = 0; c < NCHUNK_V; c++) {
        if (c + 1 < NCHUNK_V) { CP_WAIT(1); } else { CP_WAIT(0); }
        __syncthreads();
        if (c + 2 < NCHUNK_V) { load_chunk_async(c + 2, (c + 2) % 3); CP_COMMIT(); }

        const uint32_t abase = sb + (c % 3) * 32768;
        const uint32_t bbase = abase + 16384;

        #pragma unroll
        for (int ks = 0; ks < 4; ks++) {
            uint32_t af[2][4], bf[8][2];
            #pragma unroll
            for (int ia = 0; ia < 2; ia++) {
                int row = wm * 32 + ia * 16 + arow_lo;
                uint32_t cc = 2 * ks + a_cc_add;
                uint32_t addr = abase + row * 128 + ((cc << 4) ^ ((row & 7) << 4));
                ldsm4(af[ia][0], af[ia][1], af[ia][2], af[ia][3], addr);
            }
            #pragma unroll
            for (int L = 0; L < 4; L++) {
                int row = wn * 64 + L * 16 + brow_lo;
                uint32_t cc = 2 * ks + b_cc_add;
                uint32_t addr = bbase + row * 128 + ((cc << 4) ^ ((row & 7) << 4));
                ldsm4(bf[2 * L][0], bf[2 * L][1], bf[2 * L + 1][0], bf[2 * L + 1][1], addr);
            }
            #pragma unroll
            for (int ia = 0; ia < 2; ia++)
                #pragma unroll
                for (int j = 0; j < 8; j++)
                    mma16816(acc[ia][j], af[ia], bf[j]);
        }
    }

    // direct register epilogue: scale by norm, add bias, float2 stores
    const int g = lane >> 2, q = lane & 3;
    #pragma unroll
    for (int ia = 0; ia < 2; ia++) {
        int row = m0 + wm * 32 + ia * 16 + g;
        float nr0 = __ldg(&g_norm[row]);
        float nr8 = __ldg(&g_norm[row + 8]);
        #pragma unroll
        for (int j = 0; j < 8; j++) {
            int col = n0 + wn * 64 + j * 8 + q * 2;
            float b0 = __ldg(&bias[col]), b1 = __ldg(&bias[col + 1]);
            float2 v01 = make_float2(acc[ia][j][0] * nr0 + b0, acc[ia][j][1] * nr0 + b1);
            float2 v23 = make_float2(acc[ia][j][2] * nr8 + b0, acc[ia][j][3] * nr8 + b1);
            *(float2*)&g_value[(size_t)row * DD + col]       = v01;
            *(float2*)&g_value[(size_t)(row + 8) * DD + col] = v23;
        }
    }
}

// ---------------- 3) column sums of value ----------------
__global__ void __launch_bounds__(DD) sumv_part_kernel()
{
    int b = blockIdx.y, c = blockIdx.x, e = threadIdx.x;
    const float* base = g_value + (size_t)b * NN * DD + (size_t)c * 256 * DD + e;
    float s = 0.f;
    #pragma unroll 8
    for (int n = 0; n < 256; n++) s += base[(size_t)n * DD];
    g_sumv_part[(b * 16 + c) * DD + e] = s;
}
__global__ void __launch_bounds__(DD) sumv_reduce_kernel()
{
    int b = blockIdx.x, e = threadIdx.x;
    float s = 0.f;
    #pragma unroll
    for (int c = 0; c < 16; c++) s += g_sumv_part[(b * 16 + c) * DD + e];
    g_sumv[b * DD + e] = s;
}

// ---------------- 4) cos = H @ (H+L)^T  (8 chunk-pairs, 3-stage pipe, direct epilogue) ----------------
__global__ void __launch_bounds__(256, 2) cosmma_kernel(float* __restrict__ C)
{
    extern __shared__ char smem[];
    const uint32_t sb = smem_to_u32(smem);

    const int tid  = threadIdx.x;
    const int wid  = tid >> 5;
    const int lane = tid & 31;
    const int wm   = wid & 3;
    const int wn   = wid >> 2;
    const int b    = blockIdx.z;

    int i  = blockIdx.x;
    int by = (int)((sqrtf(8.f * (float)i + 1.f) - 1.f) * 0.5f);
    while ((by + 1) * (by + 2) / 2 <= i) by++;
    while (by * (by + 1) / 2 > i) by--;
    int bx = i - by * (by + 1) / 2;
    const int m0 = by * 128;
    const int n0 = bx * 128;

    const __nv_bfloat16* Agl = g_pack + ((size_t)b * NN + m0) * PACKW;
    const __nv_bfloat16* Bgl = g_pack + ((size_t)b * NN + n0) * PACKW;

    const int lr = tid >> 3;
    const int lj = tid & 7;

    auto load_chunk_async = [&](int c, int s) {
        const char* ga = (const char*)Agl + (size_t)(c & 3) * 128;   // hi only
        const char* gb = (const char*)Bgl + (size_t)c * 128;         // hi then lo
        uint32_t sa = sb + s * 32768;
        uint32_t sbm = sa + 16384;
        #pragma unroll
        for (int k = 0; k < 4; k++) {
            int r = lr + 32 * k;
            uint32_t off = r * 128 + ((lj ^ (r & 7)) << 4);
            cp_async16(sa + off,  ga + (size_t)r * (PACKW * 2) + lj * 16);
            cp_async16(sbm + off, gb + (size_t)r * (PACKW * 2) + lj * 16);
        }
    };

    float acc[2][8][4];
    #pragma unroll
    for (int ia = 0; ia < 2; ia++)
        #pragma unroll
        for (int j = 0; j < 8; j++)
            #pragma unroll
            for (int q = 0; q < 4; q++) acc[ia][j][q] = 0.f;

    const int arow_lo = (lane & 7) + ((lane >> 3) & 1) * 8;
    const int a_cc_add = (lane >> 4);
    const int brow_lo = (lane & 7) + ((lane >> 4) ? 8 : 0);
    const int b_cc_add = ((lane >> 3) & 1);

    load_chunk_async(0, 0); CP_COMMIT();
    load_chunk_async(1, 1); CP_COMMIT();

    for (int c = 0; c < NCHUNK_C; c++) {
        if (c + 1 < NCHUNK_C) { CP_WAIT(1); } else { CP_WAIT(0); }
        __syncthreads();
        if (c + 2 < NCHUNK_C) { load_chunk_async(c + 2, (c + 2) % 3); CP_COMMIT(); }

        const uint32_t abase = sb + (c % 3) * 32768;
        const uint32_t bbase = abase + 16384;

        #pragma unroll
        for (int ks = 0; ks < 4; ks++) {
            uint32_t af[2][4], bf[8][2];
            #pragma unroll
            for (int ia = 0; ia < 2; ia++) {
                int row = wm * 32 + ia * 16 + arow_lo;
                uint32_t cc = 2 * ks + a_cc_add;
                uint32_t addr = abase + row * 128 + ((cc << 4) ^ ((row & 7) << 4));
                ldsm4(af[ia][0], af[ia][1], af[ia][2], af[ia][3], addr);
            }
            #pragma unroll
            for (int L = 0; L < 4; L++) {
                int row = wn * 64 + L * 16 + brow_lo;
                uint32_t cc = 2 * ks + b_cc_add;
                uint32_t addr = bbase + row * 128 + ((cc << 4) ^ ((row & 7) << 4));
                ldsm4(bf[2 * L][0], bf[2 * L][1], bf[2 * L + 1][0], bf[2 * L + 1][1], addr);
            }
            #pragma unroll
            for (int ia = 0; ia < 2; ia++)
                #pragma unroll
                for (int j = 0; j < 8; j++)
                    mma16816(acc[ia][j], af[ia], bf[j]);
        }
    }

    // direct register epilogue: tile (float2 rows) + mirror (32B column runs)
    float* Cb = C + (size_t)b * NN * NN;
    const int g = lane >> 2, q = lane & 3;
    #pragma unroll
    for (int ia = 0; ia < 2; ia++) {
        int row = m0 + wm * 32 + ia * 16 + g;
        #pragma unroll
        for (int j = 0; j < 8; j++) {
            int col = n0 + wn * 64 + j * 8 + q * 2;
            *(float2*)&Cb[(size_t)row * NN + col]       = make_float2(acc[ia][j][0], acc[ia][j][1]);
            *(float2*)&Cb[(size_t)(row + 8) * NN + col] = make_float2(acc[ia][j][2], acc[ia][j][3]);
        }
    }
    if (bx != by) {
        #pragma unroll
        for (int ia = 0; ia < 2; ia++) {
            int row = m0 + wm * 32 + ia * 16 + g;
            #pragma unroll
            for (int j = 0; j < 8; j++) {
                int col = n0 + wn * 64 + j * 8 + q * 2;
                Cb[(size_t)col * NN + row]           = acc[ia][j][0];
                Cb[(size_t)(col + 1) * NN + row]     = acc[ia][j][1];
                Cb[(size_t)col * NN + row + 8]       = acc[ia][j][2];
                Cb[(size_t)(col + 1) * NN + row + 8] = acc[ia][j][3];
            }
        }
    }
}

// ---------------- 5) radix-select top-64 + fused sparse-softmax output ----------------
__global__ void __launch_bounds__(256) topk_out_kernel(float* __restrict__ out)
{
    const int n = blockIdx.x;
    const int b = blockIdx.y;
    const int t = threadIdx.x;

    __shared__ int      hist[256];
    __shared__ unsigned sh_prefix;
    __shared__ int      sh_krem;
    __shared__ float    red_f[8];
    __shared__ int      sel_idx[KTOP];
    __shared__ unsigned sel_key[KTOP];
    __shared__ float    sel_w[KTOP];
    __shared__ int      eq_idx[128];
    __shared__ int      cnt_gt, cnt_eq;
    __shared__ float    Zsh;

    const float* row = g_cos + ((size_t)b * NN + n) * NN;

    unsigned kreg[16];
    #pragma unroll
    for (int j = 0; j < 4; j++) {
        float4 v = *(const float4*)&row[1024 * j + 4 * t];
        const float vv[4] = {v.x, v.y, v.z, v.w};
        #pragma unroll
        for (int q = 0; q < 4; q++) {
            unsigned x = __float_as_uint(vv[q]);
            kreg[4 * j + q] = (x & 0x80000000u) ? ~x : (x | 0x80000000u);
        }
    }
    if (t == 0) { sh_prefix = 0u; sh_krem = KTOP; cnt_gt = 0; cnt_eq = 0; }
    __syncthreads();

    #pragma unroll
    for (int d = 3; d >= 0; d--) {
        hist[t] = 0;
        __syncthreads();
        const unsigned prefix = sh_prefix;
        const int krem = sh_krem;
        const int shift = d * 8;
        const unsigned mask = (d == 3) ? 0u : (0xFFFFFFFFu << (8 * (d + 1)));
        #pragma unroll
        for (int j = 0; j < 16; j++) {
            unsigned u = kreg[j];
            if ((u & mask) == prefix) atomicAdd(&hist[(u >> shift) & 0xFF], 1);
        }
        __syncthreads();
        if (t < 32) {
            int bins[8];
            int local = 0;
            #pragma unroll
            for (int i2 = 0; i2 < 8; i2++) { bins[i2] = hist[255 - 8 * t - i2]; local += bins[i2]; }
            int excl = local;
            #pragma unroll
            for (int o = 1; o < 32; o <<= 1) {
                int v = __shfl_up_sync(0xffffffffu, excl, o);
                if (t >= o) excl += v;
            }
            excl -= local;
            if (excl < krem && krem <= excl + local) {
                int run = excl, digit = 0, gt_before = excl;
                #pragma unroll
                for (int i2 = 0; i2 < 8; i2++) {
                    if (run + bins[i2] >= krem) { digit = 255 - 8 * t - i2; gt_before = run; break; }
                    run += bins[i2];
                }
                sh_prefix = prefix | ((unsigned)digit << shift);
                sh_krem = krem - gt_before;
            }
        }
        __syncthreads();
    }
    const unsigned ustar = sh_prefix;
    const int r = sh_krem;

    #pragma unroll
    for (int j = 0; j < 16; j++) {
        unsigned u = kreg[j];
        int idx = ((j >> 2) << 10) + (t << 2) + (j & 3);
        if (u > ustar) {
            int p = atomicAdd(&cnt_gt, 1);
            sel_idx[p] = idx;
            sel_key[p] = u;
        } else if (u == ustar) {
            int p = atomicAdd(&cnt_eq, 1);
            if (p < 128) eq_idx[p] = idx;
        }
    }
    __syncthreads();

    const int ngt = cnt_gt;
    if (t == 0) {
        int ne = cnt_eq < 128 ? cnt_eq : 128;
        for (int a = 1; a < ne; a++) {
            int v = eq_idx[a]; int c2 = a - 1;
            while (c2 >= 0 && eq_idx[c2] > v) { eq_idx[c2 + 1] = eq_idx[c2]; c2--; }
            eq_idx[c2 + 1] = v;
        }
        for (int a = 0; a < r; a++) { sel_idx[ngt + a] = eq_idx[a]; sel_key[ngt + a] = ustar; }
    }
    __syncthreads();

    float e_val = 0.f;
    if (t < KTOP) {
        unsigned u = sel_key[t];
        float v = (u & 0x80000000u) ? __uint_as_float(u & 0x7FFFFFFFu) : __uint_as_float(~u);
        e_val = expf(v);
        sel_w[t] = e_val - 1.0f;
    }
    float s = e_val;
    #pragma unroll
    for (int o = 16; o; o >>= 1) s += __shfl_xor_sync(0xffffffffu, s, o);
    if ((t & 31) == 0) red_f[t >> 5] = s;
    __syncthreads();
    if (t == 0) {
        float z = (float)(NN - KTOP);
        #pragma unroll
        for (int w = 0; w < 8; w++) z += red_f[w];
        Zsh = z;
    }
    __syncthreads();

    const float* Vb = g_value + (size_t)b * NN * DD;
    float acc = g_sumv[b * DD + t];
    const float invZ = 1.0f / Zsh;
    #pragma unroll 8
    for (int k = 0; k < KTOP; k++)
        acc += sel_w[k] * Vb[(size_t)sel_idx[k] * DD + t];
    out[((size_t)b * NN + n) * DD + t] = acc * invZ;
}

// ---------------- launch ----------------
extern "C" void kernel_launch(void* const* d_in, const int* in_sizes, int n_in,
                              void* d_out, int out_size)
{
    const float* x    = (const float*)d_in[0];
    const float* W    = (const float*)d_in[1];
    const float* bias = (const float*)d_in[2];
    float*       out  = (float*)d_out;

    float* p_cos;
    cudaGetSymbolAddress((void**)&p_cos, g_cos);

    const int MMA_SMEM = 3 * 32768;   // 98304: 3-stage pipeline, no epilogue staging
    cudaFuncSetAttribute(cosmma_kernel,   cudaFuncAttributeMaxDynamicSharedMemorySize, MMA_SMEM);
    cudaFuncSetAttribute(valuemma_kernel, cudaFuncAttributeMaxDynamicSharedMemorySize, MMA_SMEM);

    normalize_pack_kernel<<<BB * NN, DD>>>(x);
    wpack_kernel<<<DD, DD>>>(W);
    valuemma_kernel<<<dim3(DD / 128, (BB * NN) / 128), 256, MMA_SMEM>>>(bias);
    cosmma_kernel<<<dim3((NN / 128) * (NN / 128 + 1) / 2, 1, BB), 256, MMA_SMEM>>>(p_cos);   // launch #4 (profiler)
    sumv_part_kernel<<<dim3(16, BB), DD>>>();
    sumv_reduce_kernel<<<BB, DD>>>();
    topk_out_kernel<<<dim3(NN, BB), 256>>>(out);
}